// round 12
// baseline (speedup 1.0000x reference)
#include <cuda_runtime.h>
#include <cstdint>

// Problem constants (fixed shapes per reference)
#define Bn 16
#define Sn 4096
#define Dn 128
#define Ln 8             // timesteps per chunk (data-parallel passes)
#define NCn (Sn / Ln)    // 512 chunks per batch
#define GC 16            // chunks per group (scan hierarchy)
#define NG (NCn / GC)    // 32 groups per batch
#define TG (GC * Ln)     // 128 timesteps per group
#define LPL (TG / 32)    // 4 timesteps per lane in group scalar scan

// -------- scratch (device globals; no allocation allowed) --------
__device__ float g_m   [Bn * Sn];
__device__ float g_s   [Bn * Sn];
__device__ float g_rinv[Bn * Sn];
__device__ float g_P   [Bn * NCn * Dn];
__device__ float g_Q   [Bn * NCn * Dn];
__device__ float g_b0  [Bn * NCn * Dn];
__device__ float g_GP  [Bn * NG * Dn];
__device__ float g_GQ  [Bn * NG * Dn];
__device__ float g_laneM[Bn * NG * 32];
__device__ float g_laneS[Bn * NG * 32];
__device__ float g_GAM [Bn * NG];
__device__ float g_GAS [Bn * NG];

__device__ __forceinline__ float fsig(float x) {
    return __fdividef(1.0f, 1.0f + __expf(-x));
}

// ---- reduce-scatter: v[8] per lane -> returns sum over warp of v[lane&7] --
__device__ __forceinline__ float rs8(const float* v, int lane) {
    const bool b1 = lane & 1;
    float k0 = b1 ? v[1] : v[0], o0 = b1 ? v[0] : v[1];
    float k1 = b1 ? v[3] : v[2], o1 = b1 ? v[2] : v[3];
    float k2 = b1 ? v[5] : v[4], o2 = b1 ? v[4] : v[5];
    float k3 = b1 ? v[7] : v[6], o3 = b1 ? v[6] : v[7];
    k0 += __shfl_xor_sync(0xffffffffu, o0, 1);
    k1 += __shfl_xor_sync(0xffffffffu, o1, 1);
    k2 += __shfl_xor_sync(0xffffffffu, o2, 1);
    k3 += __shfl_xor_sync(0xffffffffu, o3, 1);
    const bool b2 = lane & 2;
    float m0 = b2 ? k1 : k0, n0 = b2 ? k0 : k1;
    float m1 = b2 ? k3 : k2, n1 = b2 ? k2 : k3;
    m0 += __shfl_xor_sync(0xffffffffu, n0, 2);
    m1 += __shfl_xor_sync(0xffffffffu, n1, 2);
    const bool b4 = lane & 4;
    float p = b4 ? m1 : m0, q = b4 ? m0 : m1;
    p += __shfl_xor_sync(0xffffffffu, q, 4);
    p += __shfl_xor_sync(0xffffffffu, p, 8);
    p += __shfl_xor_sync(0xffffffffu, p, 16);
    return p;
}

// ---- reduce-scatter: 4 values -> sum over warp of v[lane&3] ---------------
__device__ __forceinline__ float rs4(float v0, float v1, float v2, float v3,
                                     int lane) {
    const bool b1 = lane & 1;
    float k0 = b1 ? v1 : v0, o0 = b1 ? v0 : v1;
    float k1 = b1 ? v3 : v2, o1 = b1 ? v2 : v3;
    k0 += __shfl_xor_sync(0xffffffffu, o0, 1);
    k1 += __shfl_xor_sync(0xffffffffu, o1, 1);
    const bool b2 = lane & 2;
    float p = b2 ? k1 : k0, q = b2 ? k0 : k1;
    p += __shfl_xor_sync(0xffffffffu, q, 2);
    p += __shfl_xor_sync(0xffffffffu, p, 4);
    p += __shfl_xor_sync(0xffffffffu, p, 8);
    p += __shfl_xor_sync(0xffffffffu, p, 16);
    return p;
}

// ---- cache-policy loads/stores ---------------------------------------------
__device__ __forceinline__ uint64_t pol_evict_last() {
    uint64_t p;
    asm("createpolicy.fractional.L2::evict_last.b64 %0, 1.0;" : "=l"(p));
    return p;
}
__device__ __forceinline__ uint64_t pol_evict_first() {
    uint64_t p;
    asm("createpolicy.fractional.L2::evict_first.b64 %0, 1.0;" : "=l"(p));
    return p;
}
__device__ __forceinline__ float4 ldg_pol(const float4* p, uint64_t pol) {
    float4 r;
    asm("ld.global.nc.L2::cache_hint.v4.f32 {%0,%1,%2,%3}, [%4], %5;"
        : "=f"(r.x), "=f"(r.y), "=f"(r.z), "=f"(r.w)
        : "l"(p), "l"(pol));
    return r;
}
__device__ __forceinline__ void stg_stream(float4* p, float4 v) {
    asm volatile("st.global.cs.v4.f32 [%0], {%1,%2,%3,%4};"
                 :: "l"(p), "f"(v.x), "f"(v.y), "f"(v.z), "f"(v.w) : "memory");
}

// ============================================================================
// Pass A: per-chunk aggregates. One warp per (batch, chunk); lane owns 4 ch.
// __launch_bounds__(256, 5): cap regs ~51 -> 40 warps/SM theoretical.
// ============================================================================
__global__ void __launch_bounds__(256, 5)
passA_kernel(const float* __restrict__ C, const float* __restrict__ V,
             const float* __restrict__ W, const float* __restrict__ enc,
             const float* __restrict__ tmod, const float* __restrict__ cmod) {
    const int warp = (blockIdx.x * blockDim.x + threadIdx.x) >> 5;
    const int lane = threadIdx.x & 31;
    const int b = warp >> 9;
    const int k = warp & (NCn - 1);
    const int t0 = k * Ln;
    const int d4 = lane * 4;

    const uint64_t pol = pol_evict_last();

    const float4 tm = *reinterpret_cast<const float4*>(tmod + d4);
    const float4 cm = *reinterpret_cast<const float4*>(cmod + d4);
    const float4 eb = *reinterpret_cast<const float4*>(enc + b * Dn + d4);
    const float ctx0 = fsig(eb.x * cm.x) * eb.x;
    const float ctx1 = fsig(eb.y * cm.y) * eb.y;
    const float ctx2 = fsig(eb.z * cm.z) * eb.z;
    const float ctx3 = fsig(eb.w * cm.w) * eb.w;

    const size_t base = ((size_t)b * Sn + t0) * Dn + d4;
    const float4* pC = reinterpret_cast<const float4*>(C + base);
    const float4* pV = reinterpret_cast<const float4*>(V + base);
    const float4* pW = reinterpret_cast<const float4*>(W + base);

    float P0 = 1.f, P1 = 1.f, P2 = 1.f, P3 = 1.f;
    float Q0 = 0.f, Q1 = 0.f, Q2 = 0.f, Q3 = 0.f;
    float ds[Ln], es[Ln];

#pragma unroll
    for (int t = 0; t < Ln; ++t) {
        const float4 c = ldg_pol(pC + t * (Dn / 4), pol);
        const float4 v = ldg_pol(pV + t * (Dn / 4), pol);
        const float4 w = ldg_pol(pW + t * (Dn / 4), pol);

        const float dd0 = fsig(w.x * tm.x), dd1 = fsig(w.y * tm.y);
        const float dd2 = fsig(w.z * tm.z), dd3 = fsig(w.w * tm.w);
        const float e0 = __expf(c.x), e1 = __expf(c.y);
        const float e2 = __expf(c.z), e3 = __expf(c.w);

        ds[t] = (dd0 + dd1) + (dd2 + dd3);
        es[t] = (e0 + e1) + (e2 + e3);

        Q0 = fmaf(dd0, Q0, fmaf(e0, v.x, ctx0));
        Q1 = fmaf(dd1, Q1, fmaf(e1, v.y, ctx1));
        Q2 = fmaf(dd2, Q2, fmaf(e2, v.z, ctx2));
        Q3 = fmaf(dd3, Q3, fmaf(e3, v.w, ctx3));
        P0 *= dd0; P1 *= dd1; P2 *= dd2; P3 *= dd3;
    }

    const float msum = rs8(ds, lane);
    const float ssum = rs8(es, lane);
    if (lane < Ln) {
        g_m[b * Sn + t0 + lane] = msum * (1.0f / (float)Dn);
        g_s[b * Sn + t0 + lane] = ssum;
    }

    const int agg = (b * NCn + k) * Dn + d4;
    *reinterpret_cast<float4*>(&g_P[agg]) = make_float4(P0, P1, P2, P3);
    *reinterpret_cast<float4*>(&g_Q[agg]) = make_float4(Q0, Q1, Q2, Q3);
}

// ============================================================================
// Pass B1: group aggregates (parallel). One CTA per (batch, group).
// ============================================================================
__global__ void __launch_bounds__(128)
passB1_kernel() {
    const int b = blockIdx.x >> 5;
    const int g = blockIdx.x & (NG - 1);
    const int d = threadIdx.x;

    float Pr[GC], Qr[GC];
#pragma unroll
    for (int kk = 0; kk < GC; ++kk) {
        const int idx = (b * NCn + g * GC + kk) * Dn + d;
        Pr[kk] = g_P[idx];
        Qr[kk] = g_Q[idx];
    }
    float P = Pr[0], Q = Qr[0];
#pragma unroll
    for (int kk = 1; kk < GC; ++kk) {
        Q = fmaf(Pr[kk], Q, Qr[kk]);
        P *= Pr[kk];
    }
    g_GP[(b * NG + g) * Dn + d] = P;
    g_GQ[(b * NG + g) * Dn + d] = Q;

    if (threadIdx.x < 32) {
        const int lane = threadIdx.x;
        const int tb = b * Sn + g * TG + lane * LPL;
        float mr[LPL], sr[LPL];
#pragma unroll
        for (int i = 0; i < LPL; ++i) { mr[i] = g_m[tb + i]; sr[i] = g_s[tb + i]; }
        float M = mr[0], S = sr[0];
#pragma unroll
        for (int i = 1; i < LPL; ++i) { S = fmaf(mr[i], S, sr[i]); M *= mr[i]; }
#pragma unroll
        for (int off = 1; off < 32; off <<= 1) {
            const float Mp = __shfl_up_sync(0xffffffffu, M, off);
            const float Sp = __shfl_up_sync(0xffffffffu, S, off);
            if (lane >= off) { S = fmaf(M, Sp, S); M = M * Mp; }
        }
        float Mex = __shfl_up_sync(0xffffffffu, M, 1);
        float Sex = __shfl_up_sync(0xffffffffu, S, 1);
        if (lane == 0) { Mex = 1.f; Sex = 0.f; }
        g_laneM[(b * NG + g) * 32 + lane] = Mex;
        g_laneS[(b * NG + g) * 32 + lane] = Sex;
        if (lane == 31) {
            g_GAM[b * NG + g] = M;
            g_GAS[b * NG + g] = S;
        }
    }
}

// ============================================================================
// Pass B3: distribute prefixes down (parallel). One CTA per (batch, group).
// ============================================================================
__global__ void __launch_bounds__(128)
passB3_kernel() {
    const int b = blockIdx.x >> 5;
    const int g = blockIdx.x & (NG - 1);
    const int d = threadIdx.x;

    float b0 = 0.f;
    {
        float GPr[NG], GQr[NG];
#pragma unroll
        for (int gg = 0; gg < NG; ++gg) {
            const int idx = (b * NG + gg) * Dn + d;
            GPr[gg] = g_GP[idx];
            GQr[gg] = g_GQ[idx];
        }
#pragma unroll
        for (int gg = 0; gg < NG; ++gg) {
            if (gg < g) b0 = fmaf(GPr[gg], b0, GQr[gg]);
        }
    }

    {
        float Pr[GC], Qr[GC];
#pragma unroll
        for (int kk = 0; kk < GC; ++kk) {
            const int idx = (b * NCn + g * GC + kk) * Dn + d;
            Pr[kk] = g_P[idx];
            Qr[kk] = g_Q[idx];
        }
#pragma unroll
        for (int kk = 0; kk < GC; ++kk) {
            g_b0[(b * NCn + g * GC + kk) * Dn + d] = b0;
            b0 = fmaf(Pr[kk], b0, Qr[kk]);
        }
    }

    if (threadIdx.x < 32) {
        const int lane = threadIdx.x;
        float M = g_GAM[b * NG + lane];
        float S = g_GAS[b * NG + lane];
#pragma unroll
        for (int off = 1; off < 32; off <<= 1) {
            const float Mp = __shfl_up_sync(0xffffffffu, M, off);
            const float Sp = __shfl_up_sync(0xffffffffu, S, off);
            if (lane >= off) { S = fmaf(M, Sp, S); M = M * Mp; }
        }
        const float a0g = (g == 0) ? 0.f : __shfl_sync(0xffffffffu, S, g - 1);

        const float Mex = g_laneM[(b * NG + g) * 32 + lane];
        const float Sex = g_laneS[(b * NG + g) * 32 + lane];
        const int tb = b * Sn + g * TG + lane * LPL;
        float mr[LPL], sr[LPL];
#pragma unroll
        for (int i = 0; i < LPL; ++i) { mr[i] = g_m[tb + i]; sr[i] = g_s[tb + i]; }
        float a = fmaf(Mex, a0g, Sex);
#pragma unroll
        for (int i = 0; i < LPL; ++i) {
            a = fmaf(mr[i], a, sr[i]);
            g_rinv[tb + i] = __fdividef(1.0f, a + 1e-8f);
        }
    }
}

// ============================================================================
// Pass C: replay + LayerNorm. LN sums batched per 4-timestep half.
// ============================================================================
__global__ void __launch_bounds__(256)
passC_kernel(const float* __restrict__ C, const float* __restrict__ V,
             const float* __restrict__ W, const float* __restrict__ enc,
             const float* __restrict__ tmod, const float* __restrict__ cmod,
             const float* __restrict__ lnw, const float* __restrict__ lnb,
             float* __restrict__ out) {
    const int warp = (blockIdx.x * blockDim.x + threadIdx.x) >> 5;
    const int lane = threadIdx.x & 31;
    const int b = warp >> 9;
    const int k = warp & (NCn - 1);
    const int t0 = k * Ln;
    const int d4 = lane * 4;

    const uint64_t pol = pol_evict_first();

    float rv = 0.f;
    if (lane < Ln) rv = g_rinv[b * Sn + t0 + lane];

    const float4 tm = *reinterpret_cast<const float4*>(tmod + d4);
    const float4 cm = *reinterpret_cast<const float4*>(cmod + d4);
    const float4 eb = *reinterpret_cast<const float4*>(enc + b * Dn + d4);
    const float ctx0 = fsig(eb.x * cm.x) * eb.x;
    const float ctx1 = fsig(eb.y * cm.y) * eb.y;
    const float ctx2 = fsig(eb.z * cm.z) * eb.z;
    const float ctx3 = fsig(eb.w * cm.w) * eb.w;
    const float4 lw = *reinterpret_cast<const float4*>(lnw + d4);
    const float4 lb = *reinterpret_cast<const float4*>(lnb + d4);

    float4 bst = *reinterpret_cast<const float4*>(&g_b0[(b * NCn + k) * Dn + d4]);

    const size_t base = ((size_t)b * Sn + t0) * Dn + d4;
    const float4* pC = reinterpret_cast<const float4*>(C + base);
    const float4* pV = reinterpret_cast<const float4*>(V + base);
    const float4* pW = reinterpret_cast<const float4*>(W + base);
    float4* pO = reinterpret_cast<float4*>(out + base);

#pragma unroll
    for (int half = 0; half < 2; ++half) {
        float4 ot[4];
        float ls[4], lq[4];
#pragma unroll
        for (int tt = 0; tt < 4; ++tt) {
            const int t = half * 4 + tt;
            const float4 c = ldg_pol(pC + t * (Dn / 4), pol);
            const float4 v = ldg_pol(pV + t * (Dn / 4), pol);
            const float4 w = ldg_pol(pW + t * (Dn / 4), pol);

            const float dd0 = fsig(w.x * tm.x), dd1 = fsig(w.y * tm.y);
            const float dd2 = fsig(w.z * tm.z), dd3 = fsig(w.w * tm.w);
            const float e0 = __expf(c.x), e1 = __expf(c.y);
            const float e2 = __expf(c.z), e3 = __expf(c.w);

            bst.x = fmaf(dd0, bst.x, fmaf(e0, v.x, ctx0));
            bst.y = fmaf(dd1, bst.y, fmaf(e1, v.y, ctx1));
            bst.z = fmaf(dd2, bst.z, fmaf(e2, v.z, ctx2));
            bst.w = fmaf(dd3, bst.w, fmaf(e3, v.w, ctx3));

            const float rinv = __shfl_sync(0xffffffffu, rv, t);
            float4 o;
            o.x = bst.x * rinv; o.y = bst.y * rinv;
            o.z = bst.z * rinv; o.w = bst.w * rinv;
            ot[tt] = o;
            ls[tt] = (o.x + o.y) + (o.z + o.w);
            lq[tt] = fmaf(o.x, o.x, fmaf(o.y, o.y, fmaf(o.z, o.z, o.w * o.w)));
        }

        const float lsum = rs4(ls[0], ls[1], ls[2], ls[3], lane);
        const float lsq  = rs4(lq[0], lq[1], lq[2], lq[3], lane);
        const float mu   = lsum * (1.0f / (float)Dn);
        const float var  = fmaf(-mu, mu, lsq * (1.0f / (float)Dn));
        const float rstd = rsqrtf(var + 1e-5f);

#pragma unroll
        for (int tt = 0; tt < 4; ++tt) {
            const int t = half * 4 + tt;
            const float mu_t   = __shfl_sync(0xffffffffu, mu, tt);
            const float rstd_t = __shfl_sync(0xffffffffu, rstd, tt);
            float4 r;
            r.x = fmaf((ot[tt].x - mu_t) * rstd_t, lw.x, lb.x);
            r.y = fmaf((ot[tt].y - mu_t) * rstd_t, lw.y, lb.y);
            r.z = fmaf((ot[tt].z - mu_t) * rstd_t, lw.z, lb.z);
            r.w = fmaf((ot[tt].w - mu_t) * rstd_t, lw.w, lb.w);
            stg_stream(pO + t * (Dn / 4), r);
        }
    }
}

// ============================================================================
extern "C" void kernel_launch(void* const* d_in, const int* in_sizes, int n_in,
                              void* d_out, int out_size) {
    (void)in_sizes; (void)n_in; (void)out_size;
    const float* C    = (const float*)d_in[0];
    const float* V    = (const float*)d_in[1];
    const float* W    = (const float*)d_in[2];
    const float* enc  = (const float*)d_in[3];
    const float* tmod = (const float*)d_in[4];
    const float* cmod = (const float*)d_in[5];
    const float* lnw  = (const float*)d_in[6];
    const float* lnb  = (const float*)d_in[7];
    float* out = (float*)d_out;

    const int warpsTotal = Bn * NCn;            // 8192
    const int blocks = warpsTotal / 8;          // 1024 blocks of 256 threads

    passA_kernel<<<blocks, 256>>>(C, V, W, enc, tmod, cmod);
    passB1_kernel<<<Bn * NG, 128>>>();
    passB3_kernel<<<Bn * NG, 128>>>();
    passC_kernel<<<blocks, 256>>>(C, V, W, enc, tmod, cmod, lnw, lnb, out);
}

// round 13
// speedup vs baseline: 1.0861x; 1.0861x over previous
#include <cuda_runtime.h>
#include <cstdint>

// Problem constants (fixed shapes per reference)
#define Bn 16
#define Sn 4096
#define Dn 128
#define Ln 16            // timesteps per warp-chunk (single-wave sweeps)
#define NCn (Sn / Ln)    // 256 chunks per batch
#define GC 16            // chunks per group (scan hierarchy)
#define NG (NCn / GC)    // 16 groups per batch
#define TG (GC * Ln)     // 256 timesteps per group
#define LPL (TG / 32)    // 8 timesteps per lane in group scalar scan

// -------- scratch (device globals; no allocation allowed) --------
__device__ float g_m   [Bn * Sn];
__device__ float g_s   [Bn * Sn];
__device__ float g_rinv[Bn * Sn];
__device__ float g_P   [Bn * NCn * Dn];
__device__ float g_Q   [Bn * NCn * Dn];
__device__ float g_b0  [Bn * NCn * Dn];
__device__ float g_GP  [Bn * NG * Dn];
__device__ float g_GQ  [Bn * NG * Dn];
__device__ float g_laneM[Bn * NG * 32];
__device__ float g_laneS[Bn * NG * 32];
__device__ float g_GAM [Bn * NG];
__device__ float g_GAS [Bn * NG];

__device__ __forceinline__ float fsig(float x) {
    return __fdividef(1.0f, 1.0f + __expf(-x));
}

// ---- reduce-scatter: v[8] per lane -> returns sum over warp of v[lane&7] --
__device__ __forceinline__ float rs8(const float* v, int lane) {
    const bool b1 = lane & 1;
    float k0 = b1 ? v[1] : v[0], o0 = b1 ? v[0] : v[1];
    float k1 = b1 ? v[3] : v[2], o1 = b1 ? v[2] : v[3];
    float k2 = b1 ? v[5] : v[4], o2 = b1 ? v[4] : v[5];
    float k3 = b1 ? v[7] : v[6], o3 = b1 ? v[6] : v[7];
    k0 += __shfl_xor_sync(0xffffffffu, o0, 1);
    k1 += __shfl_xor_sync(0xffffffffu, o1, 1);
    k2 += __shfl_xor_sync(0xffffffffu, o2, 1);
    k3 += __shfl_xor_sync(0xffffffffu, o3, 1);
    const bool b2 = lane & 2;
    float m0 = b2 ? k1 : k0, n0 = b2 ? k0 : k1;
    float m1 = b2 ? k3 : k2, n1 = b2 ? k2 : k3;
    m0 += __shfl_xor_sync(0xffffffffu, n0, 2);
    m1 += __shfl_xor_sync(0xffffffffu, n1, 2);
    const bool b4 = lane & 4;
    float p = b4 ? m1 : m0, q = b4 ? m0 : m1;
    p += __shfl_xor_sync(0xffffffffu, q, 4);
    p += __shfl_xor_sync(0xffffffffu, p, 8);
    p += __shfl_xor_sync(0xffffffffu, p, 16);
    return p;
}

// ---- reduce-scatter: 4 values -> sum over warp of v[lane&3] ---------------
__device__ __forceinline__ float rs4(float v0, float v1, float v2, float v3,
                                     int lane) {
    const bool b1 = lane & 1;
    float k0 = b1 ? v1 : v0, o0 = b1 ? v0 : v1;
    float k1 = b1 ? v3 : v2, o1 = b1 ? v2 : v3;
    k0 += __shfl_xor_sync(0xffffffffu, o0, 1);
    k1 += __shfl_xor_sync(0xffffffffu, o1, 1);
    const bool b2 = lane & 2;
    float p = b2 ? k1 : k0, q = b2 ? k0 : k1;
    p += __shfl_xor_sync(0xffffffffu, q, 2);
    p += __shfl_xor_sync(0xffffffffu, p, 4);
    p += __shfl_xor_sync(0xffffffffu, p, 8);
    p += __shfl_xor_sync(0xffffffffu, p, 16);
    return p;
}

// ---- cache-policy loads/stores ---------------------------------------------
__device__ __forceinline__ uint64_t pol_evict_last() {
    uint64_t p;
    asm("createpolicy.fractional.L2::evict_last.b64 %0, 1.0;" : "=l"(p));
    return p;
}
__device__ __forceinline__ uint64_t pol_evict_first() {
    uint64_t p;
    asm("createpolicy.fractional.L2::evict_first.b64 %0, 1.0;" : "=l"(p));
    return p;
}
__device__ __forceinline__ float4 ldg_pol(const float4* p, uint64_t pol) {
    float4 r;
    asm("ld.global.nc.L2::cache_hint.v4.f32 {%0,%1,%2,%3}, [%4], %5;"
        : "=f"(r.x), "=f"(r.y), "=f"(r.z), "=f"(r.w)
        : "l"(p), "l"(pol));
    return r;
}
__device__ __forceinline__ void stg_stream(float4* p, float4 v) {
    asm volatile("st.global.cs.v4.f32 [%0], {%1,%2,%3,%4};"
                 :: "l"(p), "f"(v.x), "f"(v.y), "f"(v.z), "f"(v.w) : "memory");
}

// ============================================================================
// Pass A: per-chunk aggregates. One warp per (batch, chunk); lane owns 4 ch.
// Ln=16 processed as two 8-step halves (reg pressure == R9 levels).
// ============================================================================
__global__ void __launch_bounds__(256)
passA_kernel(const float* __restrict__ C, const float* __restrict__ V,
             const float* __restrict__ W, const float* __restrict__ enc,
             const float* __restrict__ tmod, const float* __restrict__ cmod) {
    const int warp = (blockIdx.x * blockDim.x + threadIdx.x) >> 5;
    const int lane = threadIdx.x & 31;
    const int b = warp >> 8;           // / NCn (=256)
    const int k = warp & (NCn - 1);
    const int t0 = k * Ln;
    const int d4 = lane * 4;

    const uint64_t pol = pol_evict_last();

    const float4 tm = *reinterpret_cast<const float4*>(tmod + d4);
    const float4 cm = *reinterpret_cast<const float4*>(cmod + d4);
    const float4 eb = *reinterpret_cast<const float4*>(enc + b * Dn + d4);
    const float ctx0 = fsig(eb.x * cm.x) * eb.x;
    const float ctx1 = fsig(eb.y * cm.y) * eb.y;
    const float ctx2 = fsig(eb.z * cm.z) * eb.z;
    const float ctx3 = fsig(eb.w * cm.w) * eb.w;

    const size_t base = ((size_t)b * Sn + t0) * Dn + d4;
    const float4* pC = reinterpret_cast<const float4*>(C + base);
    const float4* pV = reinterpret_cast<const float4*>(V + base);
    const float4* pW = reinterpret_cast<const float4*>(W + base);

    float P0 = 1.f, P1 = 1.f, P2 = 1.f, P3 = 1.f;
    float Q0 = 0.f, Q1 = 0.f, Q2 = 0.f, Q3 = 0.f;

#pragma unroll
    for (int half = 0; half < 2; ++half) {
        float ds[8], es[8];
#pragma unroll
        for (int tt = 0; tt < 8; ++tt) {
            const int t = half * 8 + tt;
            const float4 c = ldg_pol(pC + t * (Dn / 4), pol);
            const float4 v = ldg_pol(pV + t * (Dn / 4), pol);
            const float4 w = ldg_pol(pW + t * (Dn / 4), pol);

            const float dd0 = fsig(w.x * tm.x), dd1 = fsig(w.y * tm.y);
            const float dd2 = fsig(w.z * tm.z), dd3 = fsig(w.w * tm.w);
            const float e0 = __expf(c.x), e1 = __expf(c.y);
            const float e2 = __expf(c.z), e3 = __expf(c.w);

            ds[tt] = (dd0 + dd1) + (dd2 + dd3);
            es[tt] = (e0 + e1) + (e2 + e3);

            Q0 = fmaf(dd0, Q0, fmaf(e0, v.x, ctx0));
            Q1 = fmaf(dd1, Q1, fmaf(e1, v.y, ctx1));
            Q2 = fmaf(dd2, Q2, fmaf(e2, v.z, ctx2));
            Q3 = fmaf(dd3, Q3, fmaf(e3, v.w, ctx3));
            P0 *= dd0; P1 *= dd1; P2 *= dd2; P3 *= dd3;
        }
        const float msum = rs8(ds, lane);
        const float ssum = rs8(es, lane);
        if (lane < 8) {
            g_m[b * Sn + t0 + half * 8 + lane] = msum * (1.0f / (float)Dn);
            g_s[b * Sn + t0 + half * 8 + lane] = ssum;
        }
    }

    const int agg = (b * NCn + k) * Dn + d4;
    *reinterpret_cast<float4*>(&g_P[agg]) = make_float4(P0, P1, P2, P3);
    *reinterpret_cast<float4*>(&g_Q[agg]) = make_float4(Q0, Q1, Q2, Q3);
}

// ============================================================================
// Pass B1: group aggregates (parallel). One CTA per (batch, group).
// ============================================================================
__global__ void __launch_bounds__(128)
passB1_kernel() {
    const int b = blockIdx.x >> 4;       // / NG (=16)
    const int g = blockIdx.x & (NG - 1);
    const int d = threadIdx.x;

    float Pr[GC], Qr[GC];
#pragma unroll
    for (int kk = 0; kk < GC; ++kk) {
        const int idx = (b * NCn + g * GC + kk) * Dn + d;
        Pr[kk] = g_P[idx];
        Qr[kk] = g_Q[idx];
    }
    float P = Pr[0], Q = Qr[0];
#pragma unroll
    for (int kk = 1; kk < GC; ++kk) {
        Q = fmaf(Pr[kk], Q, Qr[kk]);
        P *= Pr[kk];
    }
    g_GP[(b * NG + g) * Dn + d] = P;
    g_GQ[(b * NG + g) * Dn + d] = Q;

    if (threadIdx.x < 32) {
        const int lane = threadIdx.x;
        const int tb = b * Sn + g * TG + lane * LPL;
        float mr[LPL], sr[LPL];
#pragma unroll
        for (int i = 0; i < LPL; ++i) { mr[i] = g_m[tb + i]; sr[i] = g_s[tb + i]; }
        float M = mr[0], S = sr[0];
#pragma unroll
        for (int i = 1; i < LPL; ++i) { S = fmaf(mr[i], S, sr[i]); M *= mr[i]; }
#pragma unroll
        for (int off = 1; off < 32; off <<= 1) {
            const float Mp = __shfl_up_sync(0xffffffffu, M, off);
            const float Sp = __shfl_up_sync(0xffffffffu, S, off);
            if (lane >= off) { S = fmaf(M, Sp, S); M = M * Mp; }
        }
        float Mex = __shfl_up_sync(0xffffffffu, M, 1);
        float Sex = __shfl_up_sync(0xffffffffu, S, 1);
        if (lane == 0) { Mex = 1.f; Sex = 0.f; }
        g_laneM[(b * NG + g) * 32 + lane] = Mex;
        g_laneS[(b * NG + g) * 32 + lane] = Sex;
        if (lane == 31) {
            g_GAM[b * NG + g] = M;
            g_GAS[b * NG + g] = S;
        }
    }
}

// ============================================================================
// Pass B3: distribute prefixes down (parallel). One CTA per (batch, group).
// ============================================================================
__global__ void __launch_bounds__(128)
passB3_kernel() {
    const int b = blockIdx.x >> 4;
    const int g = blockIdx.x & (NG - 1);
    const int d = threadIdx.x;

    float b0 = 0.f;
    {
        float GPr[NG], GQr[NG];
#pragma unroll
        for (int gg = 0; gg < NG; ++gg) {
            const int idx = (b * NG + gg) * Dn + d;
            GPr[gg] = g_GP[idx];
            GQr[gg] = g_GQ[idx];
        }
#pragma unroll
        for (int gg = 0; gg < NG; ++gg) {
            if (gg < g) b0 = fmaf(GPr[gg], b0, GQr[gg]);
        }
    }

    {
        float Pr[GC], Qr[GC];
#pragma unroll
        for (int kk = 0; kk < GC; ++kk) {
            const int idx = (b * NCn + g * GC + kk) * Dn + d;
            Pr[kk] = g_P[idx];
            Qr[kk] = g_Q[idx];
        }
#pragma unroll
        for (int kk = 0; kk < GC; ++kk) {
            g_b0[(b * NCn + g * GC + kk) * Dn + d] = b0;
            b0 = fmaf(Pr[kk], b0, Qr[kk]);
        }
    }

    if (threadIdx.x < 32) {
        const int lane = threadIdx.x;
        // group scan over NG=16 groups: lanes 0..15 hold aggregates
        float M = 1.f, S = 0.f;
        if (lane < NG) {
            M = g_GAM[b * NG + lane];
            S = g_GAS[b * NG + lane];
        }
#pragma unroll
        for (int off = 1; off < 16; off <<= 1) {
            const float Mp = __shfl_up_sync(0xffffffffu, M, off);
            const float Sp = __shfl_up_sync(0xffffffffu, S, off);
            if (lane >= off) { S = fmaf(M, Sp, S); M = M * Mp; }
        }
        const float a0g = (g == 0) ? 0.f : __shfl_sync(0xffffffffu, S, g - 1);

        const float Mex = g_laneM[(b * NG + g) * 32 + lane];
        const float Sex = g_laneS[(b * NG + g) * 32 + lane];
        const int tb = b * Sn + g * TG + lane * LPL;
        float mr[LPL], sr[LPL];
#pragma unroll
        for (int i = 0; i < LPL; ++i) { mr[i] = g_m[tb + i]; sr[i] = g_s[tb + i]; }
        float a = fmaf(Mex, a0g, Sex);
#pragma unroll
        for (int i = 0; i < LPL; ++i) {
            a = fmaf(mr[i], a, sr[i]);
            g_rinv[tb + i] = __fdividef(1.0f, a + 1e-8f);
        }
    }
}

// ============================================================================
// Pass C: replay + LayerNorm. Ln=16 as four 4-step quarters (R9 reg levels).
// ============================================================================
__global__ void __launch_bounds__(256)
passC_kernel(const float* __restrict__ C, const float* __restrict__ V,
             const float* __restrict__ W, const float* __restrict__ enc,
             const float* __restrict__ tmod, const float* __restrict__ cmod,
             const float* __restrict__ lnw, const float* __restrict__ lnb,
             float* __restrict__ out) {
    const int warp = (blockIdx.x * blockDim.x + threadIdx.x) >> 5;
    const int lane = threadIdx.x & 31;
    const int b = warp >> 8;
    const int k = warp & (NCn - 1);
    const int t0 = k * Ln;
    const int d4 = lane * 4;

    const uint64_t pol = pol_evict_first();

    float rv = 0.f;
    if (lane < Ln) rv = g_rinv[b * Sn + t0 + lane];

    const float4 tm = *reinterpret_cast<const float4*>(tmod + d4);
    const float4 cm = *reinterpret_cast<const float4*>(cmod + d4);
    const float4 eb = *reinterpret_cast<const float4*>(enc + b * Dn + d4);
    const float ctx0 = fsig(eb.x * cm.x) * eb.x;
    const float ctx1 = fsig(eb.y * cm.y) * eb.y;
    const float ctx2 = fsig(eb.z * cm.z) * eb.z;
    const float ctx3 = fsig(eb.w * cm.w) * eb.w;
    const float4 lw = *reinterpret_cast<const float4*>(lnw + d4);
    const float4 lb = *reinterpret_cast<const float4*>(lnb + d4);

    float4 bst = *reinterpret_cast<const float4*>(&g_b0[(b * NCn + k) * Dn + d4]);

    const size_t base = ((size_t)b * Sn + t0) * Dn + d4;
    const float4* pC = reinterpret_cast<const float4*>(C + base);
    const float4* pV = reinterpret_cast<const float4*>(V + base);
    const float4* pW = reinterpret_cast<const float4*>(W + base);
    float4* pO = reinterpret_cast<float4*>(out + base);

#pragma unroll
    for (int qr = 0; qr < 4; ++qr) {
        float4 ot[4];
        float ls[4], lq[4];
#pragma unroll
        for (int tt = 0; tt < 4; ++tt) {
            const int t = qr * 4 + tt;
            const float4 c = ldg_pol(pC + t * (Dn / 4), pol);
            const float4 v = ldg_pol(pV + t * (Dn / 4), pol);
            const float4 w = ldg_pol(pW + t * (Dn / 4), pol);

            const float dd0 = fsig(w.x * tm.x), dd1 = fsig(w.y * tm.y);
            const float dd2 = fsig(w.z * tm.z), dd3 = fsig(w.w * tm.w);
            const float e0 = __expf(c.x), e1 = __expf(c.y);
            const float e2 = __expf(c.z), e3 = __expf(c.w);

            bst.x = fmaf(dd0, bst.x, fmaf(e0, v.x, ctx0));
            bst.y = fmaf(dd1, bst.y, fmaf(e1, v.y, ctx1));
            bst.z = fmaf(dd2, bst.z, fmaf(e2, v.z, ctx2));
            bst.w = fmaf(dd3, bst.w, fmaf(e3, v.w, ctx3));

            const float rinv = __shfl_sync(0xffffffffu, rv, t);
            float4 o;
            o.x = bst.x * rinv; o.y = bst.y * rinv;
            o.z = bst.z * rinv; o.w = bst.w * rinv;
            ot[tt] = o;
            ls[tt] = (o.x + o.y) + (o.z + o.w);
            lq[tt] = fmaf(o.x, o.x, fmaf(o.y, o.y, fmaf(o.z, o.z, o.w * o.w)));
        }

        const float lsum = rs4(ls[0], ls[1], ls[2], ls[3], lane);
        const float lsq  = rs4(lq[0], lq[1], lq[2], lq[3], lane);
        const float mu   = lsum * (1.0f / (float)Dn);
        const float var  = fmaf(-mu, mu, lsq * (1.0f / (float)Dn));
        const float rstd = rsqrtf(var + 1e-5f);

#pragma unroll
        for (int tt = 0; tt < 4; ++tt) {
            const int t = qr * 4 + tt;
            const float mu_t   = __shfl_sync(0xffffffffu, mu, tt);
            const float rstd_t = __shfl_sync(0xffffffffu, rstd, tt);
            float4 r;
            r.x = fmaf((ot[tt].x - mu_t) * rstd_t, lw.x, lb.x);
            r.y = fmaf((ot[tt].y - mu_t) * rstd_t, lw.y, lb.y);
            r.z = fmaf((ot[tt].z - mu_t) * rstd_t, lw.z, lb.z);
            r.w = fmaf((ot[tt].w - mu_t) * rstd_t, lw.w, lb.w);
            stg_stream(pO + t * (Dn / 4), r);
        }
    }
}

// ============================================================================
extern "C" void kernel_launch(void* const* d_in, const int* in_sizes, int n_in,
                              void* d_out, int out_size) {
    (void)in_sizes; (void)n_in; (void)out_size;
    const float* C    = (const float*)d_in[0];
    const float* V    = (const float*)d_in[1];
    const float* W    = (const float*)d_in[2];
    const float* enc  = (const float*)d_in[3];
    const float* tmod = (const float*)d_in[4];
    const float* cmod = (const float*)d_in[5];
    const float* lnw  = (const float*)d_in[6];
    const float* lnb  = (const float*)d_in[7];
    float* out = (float*)d_out;

    const int warpsTotal = Bn * NCn;            // 4096 (single wave)
    const int blocks = warpsTotal / 8;          // 512 blocks of 256 threads

    passA_kernel<<<blocks, 256>>>(C, V, W, enc, tmod, cmod);
    passB1_kernel<<<Bn * NG, 128>>>();
    passB3_kernel<<<Bn * NG, 128>>>();
    passC_kernel<<<blocks, 256>>>(C, V, W, enc, tmod, cmod, lnw, lnb, out);
}

// round 14
// speedup vs baseline: 1.1341x; 1.0442x over previous
#include <cuda_runtime.h>
#include <cuda_fp16.h>
#include <cstdint>

// Problem constants (fixed shapes per reference)
#define Bn 16
#define Sn 4096
#define Dn 128
#define Ln 16            // timesteps per warp-chunk (single-wave sweeps)
#define NCn (Sn / Ln)    // 256 chunks per batch
#define GC 16            // chunks per group (scan hierarchy)
#define NG (NCn / GC)    // 16 groups per batch
#define TG (GC * Ln)     // 256 timesteps per group
#define LPL (TG / 32)    // 8 timesteps per lane in group scalar scan

// -------- scratch (device globals; no allocation allowed) --------
__device__ float g_m   [Bn * Sn];
__device__ float g_s   [Bn * Sn];
__device__ float g_rinv[Bn * Sn];
__device__ float g_P   [Bn * NCn * Dn];
__device__ float g_Q   [Bn * NCn * Dn];
__device__ float g_b0  [Bn * NCn * Dn];
__device__ float g_GP  [Bn * NG * Dn];
__device__ float g_GQ  [Bn * NG * Dn];
__device__ float g_laneM[Bn * NG * 32];
__device__ float g_laneS[Bn * NG * 32];
__device__ float g_GAM [Bn * NG];
__device__ float g_GAS [Bn * NG];
// packed replay operands: per (b,t,lane): dd0..3 as u16x4 (.x,.y), e*v as f16x4 (.z,.w)
__device__ uint4 g_dde [Bn * Sn * 32];        // 33.5 MB — fits in L2

__device__ __forceinline__ float fsig(float x) {
    return __fdividef(1.0f, 1.0f + __expf(-x));
}

// ---- reduce-scatter: v[8] per lane -> returns sum over warp of v[lane&7] --
__device__ __forceinline__ float rs8(const float* v, int lane) {
    const bool b1 = lane & 1;
    float k0 = b1 ? v[1] : v[0], o0 = b1 ? v[0] : v[1];
    float k1 = b1 ? v[3] : v[2], o1 = b1 ? v[2] : v[3];
    float k2 = b1 ? v[5] : v[4], o2 = b1 ? v[4] : v[5];
    float k3 = b1 ? v[7] : v[6], o3 = b1 ? v[6] : v[7];
    k0 += __shfl_xor_sync(0xffffffffu, o0, 1);
    k1 += __shfl_xor_sync(0xffffffffu, o1, 1);
    k2 += __shfl_xor_sync(0xffffffffu, o2, 1);
    k3 += __shfl_xor_sync(0xffffffffu, o3, 1);
    const bool b2 = lane & 2;
    float m0 = b2 ? k1 : k0, n0 = b2 ? k0 : k1;
    float m1 = b2 ? k3 : k2, n1 = b2 ? k2 : k3;
    m0 += __shfl_xor_sync(0xffffffffu, n0, 2);
    m1 += __shfl_xor_sync(0xffffffffu, n1, 2);
    const bool b4 = lane & 4;
    float p = b4 ? m1 : m0, q = b4 ? m0 : m1;
    p += __shfl_xor_sync(0xffffffffu, q, 4);
    p += __shfl_xor_sync(0xffffffffu, p, 8);
    p += __shfl_xor_sync(0xffffffffu, p, 16);
    return p;
}

// ---- reduce-scatter: 4 values -> sum over warp of v[lane&3] ---------------
__device__ __forceinline__ float rs4(float v0, float v1, float v2, float v3,
                                     int lane) {
    const bool b1 = lane & 1;
    float k0 = b1 ? v1 : v0, o0 = b1 ? v0 : v1;
    float k1 = b1 ? v3 : v2, o1 = b1 ? v2 : v3;
    k0 += __shfl_xor_sync(0xffffffffu, o0, 1);
    k1 += __shfl_xor_sync(0xffffffffu, o1, 1);
    const bool b2 = lane & 2;
    float p = b2 ? k1 : k0, q = b2 ? k0 : k1;
    p += __shfl_xor_sync(0xffffffffu, q, 2);
    p += __shfl_xor_sync(0xffffffffu, p, 4);
    p += __shfl_xor_sync(0xffffffffu, p, 8);
    p += __shfl_xor_sync(0xffffffffu, p, 16);
    return p;
}

// ---- cache-policy loads/stores ---------------------------------------------
__device__ __forceinline__ uint64_t pol_evict_last() {
    uint64_t p;
    asm("createpolicy.fractional.L2::evict_last.b64 %0, 1.0;" : "=l"(p));
    return p;
}
__device__ __forceinline__ uint64_t pol_evict_first() {
    uint64_t p;
    asm("createpolicy.fractional.L2::evict_first.b64 %0, 1.0;" : "=l"(p));
    return p;
}
__device__ __forceinline__ float4 ldg_pol(const float4* p, uint64_t pol) {
    float4 r;
    asm("ld.global.nc.L2::cache_hint.v4.f32 {%0,%1,%2,%3}, [%4], %5;"
        : "=f"(r.x), "=f"(r.y), "=f"(r.z), "=f"(r.w)
        : "l"(p), "l"(pol));
    return r;
}
__device__ __forceinline__ uint4 ldg_u4(const uint4* p) {
    uint4 r;
    asm("ld.global.nc.v4.u32 {%0,%1,%2,%3}, [%4];"
        : "=r"(r.x), "=r"(r.y), "=r"(r.z), "=r"(r.w) : "l"(p));
    return r;
}
__device__ __forceinline__ void stg_u4_keep(uint4* p, uint4 v, uint64_t pol) {
    asm volatile("st.global.L2::cache_hint.v4.u32 [%0], {%1,%2,%3,%4}, %5;"
                 :: "l"(p), "r"(v.x), "r"(v.y), "r"(v.z), "r"(v.w), "l"(pol)
                 : "memory");
}
__device__ __forceinline__ void stg_stream(float4* p, float4 v) {
    asm volatile("st.global.cs.v4.f32 [%0], {%1,%2,%3,%4};"
                 :: "l"(p), "f"(v.x), "f"(v.y), "f"(v.z), "f"(v.w) : "memory");
}

// ============================================================================
// Pass A: per-chunk aggregates + packed replay operands.
// One warp per (batch, chunk); lane owns 4 channels; Ln=16 in two halves.
// Input reads: evict_first (single use). dde stores: evict_last (L2-resident
// for passC, which starts ~6us later).
// ============================================================================
__global__ void __launch_bounds__(256)
passA_kernel(const float* __restrict__ C, const float* __restrict__ V,
             const float* __restrict__ W, const float* __restrict__ enc,
             const float* __restrict__ tmod, const float* __restrict__ cmod) {
    const int warp = (blockIdx.x * blockDim.x + threadIdx.x) >> 5;
    const int lane = threadIdx.x & 31;
    const int b = warp >> 8;           // / NCn (=256)
    const int k = warp & (NCn - 1);
    const int t0 = k * Ln;
    const int d4 = lane * 4;

    const uint64_t polIn = pol_evict_first();
    const uint64_t polSc = pol_evict_last();

    const float4 tm = *reinterpret_cast<const float4*>(tmod + d4);
    const float4 cm = *reinterpret_cast<const float4*>(cmod + d4);
    const float4 eb = *reinterpret_cast<const float4*>(enc + b * Dn + d4);
    const float ctx0 = fsig(eb.x * cm.x) * eb.x;
    const float ctx1 = fsig(eb.y * cm.y) * eb.y;
    const float ctx2 = fsig(eb.z * cm.z) * eb.z;
    const float ctx3 = fsig(eb.w * cm.w) * eb.w;

    const size_t base = ((size_t)b * Sn + t0) * Dn + d4;
    const float4* pC = reinterpret_cast<const float4*>(C + base);
    const float4* pV = reinterpret_cast<const float4*>(V + base);
    const float4* pW = reinterpret_cast<const float4*>(W + base);
    uint4* pD = &g_dde[((size_t)b * Sn + t0) * 32 + lane];

    float P0 = 1.f, P1 = 1.f, P2 = 1.f, P3 = 1.f;
    float Q0 = 0.f, Q1 = 0.f, Q2 = 0.f, Q3 = 0.f;

#pragma unroll
    for (int half = 0; half < 2; ++half) {
        float ds[8], es[8];
#pragma unroll
        for (int tt = 0; tt < 8; ++tt) {
            const int t = half * 8 + tt;
            const float4 c = ldg_pol(pC + t * (Dn / 4), polIn);
            const float4 v = ldg_pol(pV + t * (Dn / 4), polIn);
            const float4 w = ldg_pol(pW + t * (Dn / 4), polIn);

            const float dd0 = fsig(w.x * tm.x), dd1 = fsig(w.y * tm.y);
            const float dd2 = fsig(w.z * tm.z), dd3 = fsig(w.w * tm.w);
            const float e0 = __expf(c.x), e1 = __expf(c.y);
            const float e2 = __expf(c.z), e3 = __expf(c.w);
            const float ev0 = e0 * v.x, ev1 = e1 * v.y;
            const float ev2 = e2 * v.z, ev3 = e3 * v.w;

            ds[tt] = (dd0 + dd1) + (dd2 + dd3);
            es[tt] = (e0 + e1) + (e2 + e3);

            // pack: dd u16x4, ev f16x4
            uint4 pk;
            const uint32_t u0 = __float2uint_rn(dd0 * 65535.f);
            const uint32_t u1 = __float2uint_rn(dd1 * 65535.f);
            const uint32_t u2 = __float2uint_rn(dd2 * 65535.f);
            const uint32_t u3 = __float2uint_rn(dd3 * 65535.f);
            pk.x = u0 | (u1 << 16);
            pk.y = u2 | (u3 << 16);
            const __half2 h01 = __floats2half2_rn(ev0, ev1);
            const __half2 h23 = __floats2half2_rn(ev2, ev3);
            pk.z = *reinterpret_cast<const uint32_t*>(&h01);
            pk.w = *reinterpret_cast<const uint32_t*>(&h23);
            stg_u4_keep(pD + t * 32, pk, polSc);

            Q0 = fmaf(dd0, Q0, ev0 + ctx0);
            Q1 = fmaf(dd1, Q1, ev1 + ctx1);
            Q2 = fmaf(dd2, Q2, ev2 + ctx2);
            Q3 = fmaf(dd3, Q3, ev3 + ctx3);
            P0 *= dd0; P1 *= dd1; P2 *= dd2; P3 *= dd3;
        }
        const float msum = rs8(ds, lane);
        const float ssum = rs8(es, lane);
        if (lane < 8) {
            g_m[b * Sn + t0 + half * 8 + lane] = msum * (1.0f / (float)Dn);
            g_s[b * Sn + t0 + half * 8 + lane] = ssum;
        }
    }

    const int agg = (b * NCn + k) * Dn + d4;
    *reinterpret_cast<float4*>(&g_P[agg]) = make_float4(P0, P1, P2, P3);
    *reinterpret_cast<float4*>(&g_Q[agg]) = make_float4(Q0, Q1, Q2, Q3);
}

// ============================================================================
// Pass B1: group aggregates (parallel). One CTA per (batch, group).
// ============================================================================
__global__ void __launch_bounds__(128)
passB1_kernel() {
    const int b = blockIdx.x >> 4;       // / NG (=16)
    const int g = blockIdx.x & (NG - 1);
    const int d = threadIdx.x;

    float Pr[GC], Qr[GC];
#pragma unroll
    for (int kk = 0; kk < GC; ++kk) {
        const int idx = (b * NCn + g * GC + kk) * Dn + d;
        Pr[kk] = g_P[idx];
        Qr[kk] = g_Q[idx];
    }
    float P = Pr[0], Q = Qr[0];
#pragma unroll
    for (int kk = 1; kk < GC; ++kk) {
        Q = fmaf(Pr[kk], Q, Qr[kk]);
        P *= Pr[kk];
    }
    g_GP[(b * NG + g) * Dn + d] = P;
    g_GQ[(b * NG + g) * Dn + d] = Q;

    if (threadIdx.x < 32) {
        const int lane = threadIdx.x;
        const int tb = b * Sn + g * TG + lane * LPL;
        float mr[LPL], sr[LPL];
#pragma unroll
        for (int i = 0; i < LPL; ++i) { mr[i] = g_m[tb + i]; sr[i] = g_s[tb + i]; }
        float M = mr[0], S = sr[0];
#pragma unroll
        for (int i = 1; i < LPL; ++i) { S = fmaf(mr[i], S, sr[i]); M *= mr[i]; }
#pragma unroll
        for (int off = 1; off < 32; off <<= 1) {
            const float Mp = __shfl_up_sync(0xffffffffu, M, off);
            const float Sp = __shfl_up_sync(0xffffffffu, S, off);
            if (lane >= off) { S = fmaf(M, Sp, S); M = M * Mp; }
        }
        float Mex = __shfl_up_sync(0xffffffffu, M, 1);
        float Sex = __shfl_up_sync(0xffffffffu, S, 1);
        if (lane == 0) { Mex = 1.f; Sex = 0.f; }
        g_laneM[(b * NG + g) * 32 + lane] = Mex;
        g_laneS[(b * NG + g) * 32 + lane] = Sex;
        if (lane == 31) {
            g_GAM[b * NG + g] = M;
            g_GAS[b * NG + g] = S;
        }
    }
}

// ============================================================================
// Pass B3: distribute prefixes down (parallel). One CTA per (batch, group).
// ============================================================================
__global__ void __launch_bounds__(128)
passB3_kernel() {
    const int b = blockIdx.x >> 4;
    const int g = blockIdx.x & (NG - 1);
    const int d = threadIdx.x;

    float b0 = 0.f;
    {
        float GPr[NG], GQr[NG];
#pragma unroll
        for (int gg = 0; gg < NG; ++gg) {
            const int idx = (b * NG + gg) * Dn + d;
            GPr[gg] = g_GP[idx];
            GQr[gg] = g_GQ[idx];
        }
#pragma unroll
        for (int gg = 0; gg < NG; ++gg) {
            if (gg < g) b0 = fmaf(GPr[gg], b0, GQr[gg]);
        }
    }

    {
        float Pr[GC], Qr[GC];
#pragma unroll
        for (int kk = 0; kk < GC; ++kk) {
            const int idx = (b * NCn + g * GC + kk) * Dn + d;
            Pr[kk] = g_P[idx];
            Qr[kk] = g_Q[idx];
        }
#pragma unroll
        for (int kk = 0; kk < GC; ++kk) {
            g_b0[(b * NCn + g * GC + kk) * Dn + d] = b0;
            b0 = fmaf(Pr[kk], b0, Qr[kk]);
        }
    }

    if (threadIdx.x < 32) {
        const int lane = threadIdx.x;
        float M = 1.f, S = 0.f;
        if (lane < NG) {
            M = g_GAM[b * NG + lane];
            S = g_GAS[b * NG + lane];
        }
#pragma unroll
        for (int off = 1; off < 16; off <<= 1) {
            const float Mp = __shfl_up_sync(0xffffffffu, M, off);
            const float Sp = __shfl_up_sync(0xffffffffu, S, off);
            if (lane >= off) { S = fmaf(M, Sp, S); M = M * Mp; }
        }
        const float a0g = (g == 0) ? 0.f : __shfl_sync(0xffffffffu, S, g - 1);

        const float Mex = g_laneM[(b * NG + g) * 32 + lane];
        const float Sex = g_laneS[(b * NG + g) * 32 + lane];
        const int tb = b * Sn + g * TG + lane * LPL;
        float mr[LPL], sr[LPL];
#pragma unroll
        for (int i = 0; i < LPL; ++i) { mr[i] = g_m[tb + i]; sr[i] = g_s[tb + i]; }
        float a = fmaf(Mex, a0g, Sex);
#pragma unroll
        for (int i = 0; i < LPL; ++i) {
            a = fmaf(mr[i], a, sr[i]);
            g_rinv[tb + i] = __fdividef(1.0f, a + 1e-8f);
        }
    }
}

// ============================================================================
// Pass C: replay from packed dde (mostly L2-resident) + LayerNorm.
// No sigmoid/exp; reads 33.5 MB instead of 100.6 MB.
// ============================================================================
__global__ void __launch_bounds__(256)
passC_kernel(const float* __restrict__ enc, const float* __restrict__ cmod,
             const float* __restrict__ lnw, const float* __restrict__ lnb,
             float* __restrict__ out) {
    const int warp = (blockIdx.x * blockDim.x + threadIdx.x) >> 5;
    const int lane = threadIdx.x & 31;
    const int b = warp >> 8;
    const int k = warp & (NCn - 1);
    const int t0 = k * Ln;
    const int d4 = lane * 4;

    float rv = 0.f;
    if (lane < Ln) rv = g_rinv[b * Sn + t0 + lane];

    const float4 cm = *reinterpret_cast<const float4*>(cmod + d4);
    const float4 eb = *reinterpret_cast<const float4*>(enc + b * Dn + d4);
    const float ctx0 = fsig(eb.x * cm.x) * eb.x;
    const float ctx1 = fsig(eb.y * cm.y) * eb.y;
    const float ctx2 = fsig(eb.z * cm.z) * eb.z;
    const float ctx3 = fsig(eb.w * cm.w) * eb.w;
    const float4 lw = *reinterpret_cast<const float4*>(lnw + d4);
    const float4 lb = *reinterpret_cast<const float4*>(lnb + d4);

    float4 bst = *reinterpret_cast<const float4*>(&g_b0[(b * NCn + k) * Dn + d4]);

    const uint4* pD = &g_dde[((size_t)b * Sn + t0) * 32 + lane];
    float4* pO = reinterpret_cast<float4*>(out + ((size_t)b * Sn + t0) * Dn + d4);

    const float inv16 = 1.0f / 65535.f;

#pragma unroll
    for (int qr = 0; qr < 4; ++qr) {
        float4 ot[4];
        float ls[4], lq[4];
#pragma unroll
        for (int tt = 0; tt < 4; ++tt) {
            const int t = qr * 4 + tt;
            const uint4 pk = ldg_u4(pD + t * 32);

            const float dd0 = (float)(pk.x & 0xffffu) * inv16;
            const float dd1 = (float)(pk.x >> 16) * inv16;
            const float dd2 = (float)(pk.y & 0xffffu) * inv16;
            const float dd3 = (float)(pk.y >> 16) * inv16;
            const float2 e01 = __half22float2(*reinterpret_cast<const __half2*>(&pk.z));
            const float2 e23 = __half22float2(*reinterpret_cast<const __half2*>(&pk.w));

            bst.x = fmaf(dd0, bst.x, e01.x + ctx0);
            bst.y = fmaf(dd1, bst.y, e01.y + ctx1);
            bst.z = fmaf(dd2, bst.z, e23.x + ctx2);
            bst.w = fmaf(dd3, bst.w, e23.y + ctx3);

            const float rinv = __shfl_sync(0xffffffffu, rv, t);
            float4 o;
            o.x = bst.x * rinv; o.y = bst.y * rinv;
            o.z = bst.z * rinv; o.w = bst.w * rinv;
            ot[tt] = o;
            ls[tt] = (o.x + o.y) + (o.z + o.w);
            lq[tt] = fmaf(o.x, o.x, fmaf(o.y, o.y, fmaf(o.z, o.z, o.w * o.w)));
        }

        const float lsum = rs4(ls[0], ls[1], ls[2], ls[3], lane);
        const float lsq  = rs4(lq[0], lq[1], lq[2], lq[3], lane);
        const float mu   = lsum * (1.0f / (float)Dn);
        const float var  = fmaf(-mu, mu, lsq * (1.0f / (float)Dn));
        const float rstd = rsqrtf(var + 1e-5f);

#pragma unroll
        for (int tt = 0; tt < 4; ++tt) {
            const int t = qr * 4 + tt;
            const float mu_t   = __shfl_sync(0xffffffffu, mu, tt);
            const float rstd_t = __shfl_sync(0xffffffffu, rstd, tt);
            float4 r;
            r.x = fmaf((ot[tt].x - mu_t) * rstd_t, lw.x, lb.x);
            r.y = fmaf((ot[tt].y - mu_t) * rstd_t, lw.y, lb.y);
            r.z = fmaf((ot[tt].z - mu_t) * rstd_t, lw.z, lb.z);
            r.w = fmaf((ot[tt].w - mu_t) * rstd_t, lw.w, lb.w);
            stg_stream(pO + t * (Dn / 4), r);
        }
    }
}

// ============================================================================
extern "C" void kernel_launch(void* const* d_in, const int* in_sizes, int n_in,
                              void* d_out, int out_size) {
    (void)in_sizes; (void)n_in; (void)out_size;
    const float* C    = (const float*)d_in[0];
    const float* V    = (const float*)d_in[1];
    const float* W    = (const float*)d_in[2];
    const float* enc  = (const float*)d_in[3];
    const float* tmod = (const float*)d_in[4];
    const float* cmod = (const float*)d_in[5];
    const float* lnw  = (const float*)d_in[6];
    const float* lnb  = (const float*)d_in[7];
    float* out = (float*)d_out;

    const int warpsTotal = Bn * NCn;            // 4096 (single wave)
    const int blocks = warpsTotal / 8;          // 512 blocks of 256 threads

    passA_kernel<<<blocks, 256>>>(C, V, W, enc, tmod, cmod);
    passB1_kernel<<<Bn * NG, 128>>>();
    passB3_kernel<<<Bn * NG, 128>>>();
    passC_kernel<<<blocks, 256>>>(enc, cmod, lnw, lnb, out);
}

// round 15
// speedup vs baseline: 1.3003x; 1.1465x over previous
#include <cuda_runtime.h>
#include <cuda_fp16.h>
#include <cstdint>

// Problem constants (fixed shapes per reference)
#define Bn 16
#define Sn 4096
#define Dn 128
#define Ln 16            // timesteps per warp-chunk
#define NCn (Sn / Ln)    // 256 chunks per batch
#define GC 16            // chunks per group (scan hierarchy)
#define NG (NCn / GC)    // 16 groups per batch
#define TG (GC * Ln)     // 256 timesteps per group
#define LPL (TG / 32)    // 8 timesteps per lane in group scalar scan

// -------- scratch (device globals; no allocation allowed) --------
__device__ float g_m   [Bn * Sn];
__device__ float g_s   [Bn * Sn];
__device__ float g_rinv[Bn * Sn];
__device__ float g_P   [Bn * NCn * Dn];
__device__ float g_Q   [Bn * NCn * Dn];
__device__ float g_b0  [Bn * NCn * Dn];
__device__ float g_GP  [Bn * NG * Dn];
__device__ float g_GQ  [Bn * NG * Dn];
__device__ float g_laneM[Bn * NG * 32];
__device__ float g_laneS[Bn * NG * 32];
__device__ float g_GAM [Bn * NG];
__device__ float g_GAS [Bn * NG];
// packed replay operands: per (b,t,lane): dd0..3 as u16x4 (.x,.y), e*v as f16x4 (.z,.w)
__device__ uint4 g_dde [Bn * Sn * 32];        // 33.5 MB — fits in L2

__device__ __forceinline__ float fsig(float x) {
    return __fdividef(1.0f, 1.0f + __expf(-x));
}

// ---- reduce-scatter: v[8] per lane -> returns sum over warp of v[lane&7] --
__device__ __forceinline__ float rs8(const float* v, int lane) {
    const bool b1 = lane & 1;
    float k0 = b1 ? v[1] : v[0], o0 = b1 ? v[0] : v[1];
    float k1 = b1 ? v[3] : v[2], o1 = b1 ? v[2] : v[3];
    float k2 = b1 ? v[5] : v[4], o2 = b1 ? v[4] : v[5];
    float k3 = b1 ? v[7] : v[6], o3 = b1 ? v[6] : v[7];
    k0 += __shfl_xor_sync(0xffffffffu, o0, 1);
    k1 += __shfl_xor_sync(0xffffffffu, o1, 1);
    k2 += __shfl_xor_sync(0xffffffffu, o2, 1);
    k3 += __shfl_xor_sync(0xffffffffu, o3, 1);
    const bool b2 = lane & 2;
    float m0 = b2 ? k1 : k0, n0 = b2 ? k0 : k1;
    float m1 = b2 ? k3 : k2, n1 = b2 ? k2 : k3;
    m0 += __shfl_xor_sync(0xffffffffu, n0, 2);
    m1 += __shfl_xor_sync(0xffffffffu, n1, 2);
    const bool b4 = lane & 4;
    float p = b4 ? m1 : m0, q = b4 ? m0 : m1;
    p += __shfl_xor_sync(0xffffffffu, q, 4);
    p += __shfl_xor_sync(0xffffffffu, p, 8);
    p += __shfl_xor_sync(0xffffffffu, p, 16);
    return p;
}

// ---- reduce-scatter: 4 values -> sum over warp of v[lane&3] ---------------
__device__ __forceinline__ float rs4(float v0, float v1, float v2, float v3,
                                     int lane) {
    const bool b1 = lane & 1;
    float k0 = b1 ? v1 : v0, o0 = b1 ? v0 : v1;
    float k1 = b1 ? v3 : v2, o1 = b1 ? v2 : v3;
    k0 += __shfl_xor_sync(0xffffffffu, o0, 1);
    k1 += __shfl_xor_sync(0xffffffffu, o1, 1);
    const bool b2 = lane & 2;
    float p = b2 ? k1 : k0, q = b2 ? k0 : k1;
    p += __shfl_xor_sync(0xffffffffu, q, 2);
    p += __shfl_xor_sync(0xffffffffu, p, 4);
    p += __shfl_xor_sync(0xffffffffu, p, 8);
    p += __shfl_xor_sync(0xffffffffu, p, 16);
    return p;
}

// ---- cache-policy loads/stores ---------------------------------------------
__device__ __forceinline__ uint64_t pol_evict_last() {
    uint64_t p;
    asm("createpolicy.fractional.L2::evict_last.b64 %0, 1.0;" : "=l"(p));
    return p;
}
__device__ __forceinline__ uint64_t pol_evict_first() {
    uint64_t p;
    asm("createpolicy.fractional.L2::evict_first.b64 %0, 1.0;" : "=l"(p));
    return p;
}
__device__ __forceinline__ float4 ldg_pol(const float4* p, uint64_t pol) {
    float4 r;
    asm("ld.global.nc.L2::cache_hint.v4.f32 {%0,%1,%2,%3}, [%4], %5;"
        : "=f"(r.x), "=f"(r.y), "=f"(r.z), "=f"(r.w)
        : "l"(p), "l"(pol));
    return r;
}
__device__ __forceinline__ uint4 ldg_u4(const uint4* p) {
    uint4 r;
    asm("ld.global.nc.v4.u32 {%0,%1,%2,%3}, [%4];"
        : "=r"(r.x), "=r"(r.y), "=r"(r.z), "=r"(r.w) : "l"(p));
    return r;
}
__device__ __forceinline__ void stg_u4_keep(uint4* p, uint4 v, uint64_t pol) {
    asm volatile("st.global.L2::cache_hint.v4.u32 [%0], {%1,%2,%3,%4}, %5;"
                 :: "l"(p), "r"(v.x), "r"(v.y), "r"(v.z), "r"(v.w), "l"(pol)
                 : "memory");
}
__device__ __forceinline__ void stg_stream(float4* p, float4 v) {
    asm volatile("st.global.cs.v4.f32 [%0], {%1,%2,%3,%4};"
                 :: "l"(p), "f"(v.x), "f"(v.y), "f"(v.z), "f"(v.w) : "memory");
}

// ============================================================================
// Pass A (+B1 folded): CTA = 512 threads = 16 warps = ONE scan group.
// Each warp handles one chunk (Ln=16, two 8-step halves). After the main
// loop the CTA computes group aggregates in-CTA (smem + warp scans),
// eliminating the separate B1 kernel.
// ============================================================================
__global__ void __launch_bounds__(512)
passA_kernel(const float* __restrict__ C, const float* __restrict__ V,
             const float* __restrict__ W, const float* __restrict__ enc,
             const float* __restrict__ tmod, const float* __restrict__ cmod) {
    __shared__ float sP[GC * Dn];     // per-chunk vector P (8 KB)
    __shared__ float sQ[GC * Dn];     // per-chunk vector Q (8 KB)
    __shared__ float sM2[32], sS2[32];  // per-half-chunk scalar aggregates

    const int wid  = threadIdx.x >> 5;
    const int lane = threadIdx.x & 31;
    const int b = blockIdx.x >> 4;          // / NG
    const int g = blockIdx.x & (NG - 1);
    const int k = g * GC + wid;
    const int t0 = k * Ln;
    const int d4 = lane * 4;

    const uint64_t polIn = pol_evict_first();
    const uint64_t polSc = pol_evict_last();

    const float4 tm = *reinterpret_cast<const float4*>(tmod + d4);
    const float4 cm = *reinterpret_cast<const float4*>(cmod + d4);
    const float4 eb = *reinterpret_cast<const float4*>(enc + b * Dn + d4);
    const float ctx0 = fsig(eb.x * cm.x) * eb.x;
    const float ctx1 = fsig(eb.y * cm.y) * eb.y;
    const float ctx2 = fsig(eb.z * cm.z) * eb.z;
    const float ctx3 = fsig(eb.w * cm.w) * eb.w;

    const size_t base = ((size_t)b * Sn + t0) * Dn + d4;
    const float4* pC = reinterpret_cast<const float4*>(C + base);
    const float4* pV = reinterpret_cast<const float4*>(V + base);
    const float4* pW = reinterpret_cast<const float4*>(W + base);
    uint4* pD = &g_dde[((size_t)b * Sn + t0) * 32 + lane];

    float P0 = 1.f, P1 = 1.f, P2 = 1.f, P3 = 1.f;
    float Q0 = 0.f, Q1 = 0.f, Q2 = 0.f, Q3 = 0.f;

#pragma unroll
    for (int half = 0; half < 2; ++half) {
        float ds[8], es[8];
#pragma unroll
        for (int tt = 0; tt < 8; ++tt) {
            const int t = half * 8 + tt;
            const float4 c = ldg_pol(pC + t * (Dn / 4), polIn);
            const float4 v = ldg_pol(pV + t * (Dn / 4), polIn);
            const float4 w = ldg_pol(pW + t * (Dn / 4), polIn);

            const float dd0 = fsig(w.x * tm.x), dd1 = fsig(w.y * tm.y);
            const float dd2 = fsig(w.z * tm.z), dd3 = fsig(w.w * tm.w);
            const float e0 = __expf(c.x), e1 = __expf(c.y);
            const float e2 = __expf(c.z), e3 = __expf(c.w);
            const float ev0 = e0 * v.x, ev1 = e1 * v.y;
            const float ev2 = e2 * v.z, ev3 = e3 * v.w;

            ds[tt] = (dd0 + dd1) + (dd2 + dd3);
            es[tt] = (e0 + e1) + (e2 + e3);

            uint4 pk;
            const uint32_t u0 = __float2uint_rn(dd0 * 65535.f);
            const uint32_t u1 = __float2uint_rn(dd1 * 65535.f);
            const uint32_t u2 = __float2uint_rn(dd2 * 65535.f);
            const uint32_t u3 = __float2uint_rn(dd3 * 65535.f);
            pk.x = u0 | (u1 << 16);
            pk.y = u2 | (u3 << 16);
            const __half2 h01 = __floats2half2_rn(ev0, ev1);
            const __half2 h23 = __floats2half2_rn(ev2, ev3);
            pk.z = *reinterpret_cast<const uint32_t*>(&h01);
            pk.w = *reinterpret_cast<const uint32_t*>(&h23);
            stg_u4_keep(pD + t * 32, pk, polSc);

            Q0 = fmaf(dd0, Q0, ev0 + ctx0);
            Q1 = fmaf(dd1, Q1, ev1 + ctx1);
            Q2 = fmaf(dd2, Q2, ev2 + ctx2);
            Q3 = fmaf(dd3, Q3, ev3 + ctx3);
            P0 *= dd0; P1 *= dd1; P2 *= dd2; P3 *= dd3;
        }
        const float msum = rs8(ds, lane);   // lane l holds sum for t = l&7
        const float ssum = rs8(es, lane);
        if (lane < 8) {
            g_m[b * Sn + t0 + half * 8 + lane] = msum * (1.0f / (float)Dn);
            g_s[b * Sn + t0 + half * 8 + lane] = ssum;
        }
        // half-chunk scalar aggregate: affine scan over 8 t's (octet scan;
        // data replicated every 8 lanes so shfl_up with (lane&7) guard works)
        {
            float M = msum * (1.0f / (float)Dn);
            float S = ssum;
#pragma unroll
            for (int off = 1; off < 8; off <<= 1) {
                const float Mp = __shfl_up_sync(0xffffffffu, M, off);
                const float Sp = __shfl_up_sync(0xffffffffu, S, off);
                if ((lane & 7) >= off) { S = fmaf(M, Sp, S); M = M * Mp; }
            }
            if (lane == 7) { sM2[wid * 2 + half] = M; sS2[wid * 2 + half] = S; }
        }
    }

    // per-chunk P/Q: to global (B3/passC) and to smem (group aggregate)
    const int agg = (b * NCn + k) * Dn + d4;
    *reinterpret_cast<float4*>(&g_P[agg]) = make_float4(P0, P1, P2, P3);
    *reinterpret_cast<float4*>(&g_Q[agg]) = make_float4(Q0, Q1, Q2, Q3);
    *reinterpret_cast<float4*>(&sP[wid * Dn + d4]) = make_float4(P0, P1, P2, P3);
    *reinterpret_cast<float4*>(&sQ[wid * Dn + d4]) = make_float4(Q0, Q1, Q2, Q3);
    __syncthreads();

    // ---- group vector aggregate (threads 0..127, channel d) ----
    if (threadIdx.x < Dn) {
        const int d = threadIdx.x;
        float P = 1.f, Q = 0.f;
#pragma unroll
        for (int w = 0; w < GC; ++w) {
            const float Pw = sP[w * Dn + d];
            const float Qw = sQ[w * Dn + d];
            Q = fmaf(Pw, Q, Qw);
            P *= Pw;
        }
        g_GP[(b * NG + g) * Dn + d] = P;
        g_GQ[(b * NG + g) * Dn + d] = Q;
    }

    // ---- group scalar scan (warp 16's lanes? use first warp of last 128) --
    if (threadIdx.x >= Dn && threadIdx.x < Dn + 32) {
        const int l = threadIdx.x - Dn;   // 0..31 — these are lanes of warp 4
        float M = sM2[l], S = sS2[l];
#pragma unroll
        for (int off = 1; off < 32; off <<= 1) {
            const float Mp = __shfl_up_sync(0xffffffffu, M, off);
            const float Sp = __shfl_up_sync(0xffffffffu, S, off);
            if (l >= off) { S = fmaf(M, Sp, S); M = M * Mp; }
        }
        float Mex = __shfl_up_sync(0xffffffffu, M, 1);
        float Sex = __shfl_up_sync(0xffffffffu, S, 1);
        if (l == 0) { Mex = 1.f; Sex = 0.f; }
        g_laneM[(b * NG + g) * 32 + l] = Mex;
        g_laneS[(b * NG + g) * 32 + l] = Sex;
        if (l == 31) {
            g_GAM[b * NG + g] = M;
            g_GAS[b * NG + g] = S;
        }
    }
}

// ============================================================================
// Pass B3: distribute prefixes down (parallel). One CTA per (batch, group).
// ============================================================================
__global__ void __launch_bounds__(128)
passB3_kernel() {
    const int b = blockIdx.x >> 4;
    const int g = blockIdx.x & (NG - 1);
    const int d = threadIdx.x;

    float b0 = 0.f;
    {
        float GPr[NG], GQr[NG];
#pragma unroll
        for (int gg = 0; gg < NG; ++gg) {
            const int idx = (b * NG + gg) * Dn + d;
            GPr[gg] = g_GP[idx];
            GQr[gg] = g_GQ[idx];
        }
#pragma unroll
        for (int gg = 0; gg < NG; ++gg) {
            if (gg < g) b0 = fmaf(GPr[gg], b0, GQr[gg]);
        }
    }

    {
        float Pr[GC], Qr[GC];
#pragma unroll
        for (int kk = 0; kk < GC; ++kk) {
            const int idx = (b * NCn + g * GC + kk) * Dn + d;
            Pr[kk] = g_P[idx];
            Qr[kk] = g_Q[idx];
        }
#pragma unroll
        for (int kk = 0; kk < GC; ++kk) {
            g_b0[(b * NCn + g * GC + kk) * Dn + d] = b0;
            b0 = fmaf(Pr[kk], b0, Qr[kk]);
        }
    }

    if (threadIdx.x < 32) {
        const int lane = threadIdx.x;
        float M = 1.f, S = 0.f;
        if (lane < NG) {
            M = g_GAM[b * NG + lane];
            S = g_GAS[b * NG + lane];
        }
#pragma unroll
        for (int off = 1; off < 16; off <<= 1) {
            const float Mp = __shfl_up_sync(0xffffffffu, M, off);
            const float Sp = __shfl_up_sync(0xffffffffu, S, off);
            if (lane >= off) { S = fmaf(M, Sp, S); M = M * Mp; }
        }
        const float a0g = (g == 0) ? 0.f : __shfl_sync(0xffffffffu, S, g - 1);

        const float Mex = g_laneM[(b * NG + g) * 32 + lane];
        const float Sex = g_laneS[(b * NG + g) * 32 + lane];
        const int tb = b * Sn + g * TG + lane * LPL;
        float mr[LPL], sr[LPL];
#pragma unroll
        for (int i = 0; i < LPL; ++i) { mr[i] = g_m[tb + i]; sr[i] = g_s[tb + i]; }
        float a = fmaf(Mex, a0g, Sex);
#pragma unroll
        for (int i = 0; i < LPL; ++i) {
            a = fmaf(mr[i], a, sr[i]);
            g_rinv[tb + i] = __fdividef(1.0f, a + 1e-8f);
        }
    }
}

// ============================================================================
// Pass C: replay from packed dde (mostly L2-resident) + LayerNorm.
// ============================================================================
__global__ void __launch_bounds__(256)
passC_kernel(const float* __restrict__ enc, const float* __restrict__ cmod,
             const float* __restrict__ lnw, const float* __restrict__ lnb,
             float* __restrict__ out) {
    const int warp = (blockIdx.x * blockDim.x + threadIdx.x) >> 5;
    const int lane = threadIdx.x & 31;
    const int b = warp >> 8;
    const int k = warp & (NCn - 1);
    const int t0 = k * Ln;
    const int d4 = lane * 4;

    float rv = 0.f;
    if (lane < Ln) rv = g_rinv[b * Sn + t0 + lane];

    const float4 cm = *reinterpret_cast<const float4*>(cmod + d4);
    const float4 eb = *reinterpret_cast<const float4*>(enc + b * Dn + d4);
    const float ctx0 = fsig(eb.x * cm.x) * eb.x;
    const float ctx1 = fsig(eb.y * cm.y) * eb.y;
    const float ctx2 = fsig(eb.z * cm.z) * eb.z;
    const float ctx3 = fsig(eb.w * cm.w) * eb.w;
    const float4 lw = *reinterpret_cast<const float4*>(lnw + d4);
    const float4 lb = *reinterpret_cast<const float4*>(lnb + d4);

    float4 bst = *reinterpret_cast<const float4*>(&g_b0[(b * NCn + k) * Dn + d4]);

    const uint4* pD = &g_dde[((size_t)b * Sn + t0) * 32 + lane];
    float4* pO = reinterpret_cast<float4*>(out + ((size_t)b * Sn + t0) * Dn + d4);

    const float inv16 = 1.0f / 65535.f;

#pragma unroll
    for (int qr = 0; qr < 4; ++qr) {
        float4 ot[4];
        float ls[4], lq[4];
#pragma unroll
        for (int tt = 0; tt < 4; ++tt) {
            const int t = qr * 4 + tt;
            const uint4 pk = ldg_u4(pD + t * 32);

            const float dd0 = (float)(pk.x & 0xffffu) * inv16;
            const float dd1 = (float)(pk.x >> 16) * inv16;
            const float dd2 = (float)(pk.y & 0xffffu) * inv16;
            const float dd3 = (float)(pk.y >> 16) * inv16;
            const float2 e01 = __half22float2(*reinterpret_cast<const __half2*>(&pk.z));
            const float2 e23 = __half22float2(*reinterpret_cast<const __half2*>(&pk.w));

            bst.x = fmaf(dd0, bst.x, e01.x + ctx0);
            bst.y = fmaf(dd1, bst.y, e01.y + ctx1);
            bst.z = fmaf(dd2, bst.z, e23.x + ctx2);
            bst.w = fmaf(dd3, bst.w, e23.y + ctx3);

            const float rinv = __shfl_sync(0xffffffffu, rv, t);
            float4 o;
            o.x = bst.x * rinv; o.y = bst.y * rinv;
            o.z = bst.z * rinv; o.w = bst.w * rinv;
            ot[tt] = o;
            ls[tt] = (o.x + o.y) + (o.z + o.w);
            lq[tt] = fmaf(o.x, o.x, fmaf(o.y, o.y, fmaf(o.z, o.z, o.w * o.w)));
        }

        const float lsum = rs4(ls[0], ls[1], ls[2], ls[3], lane);
        const float lsq  = rs4(lq[0], lq[1], lq[2], lq[3], lane);
        const float mu   = lsum * (1.0f / (float)Dn);
        const float var  = fmaf(-mu, mu, lsq * (1.0f / (float)Dn));
        const float rstd = rsqrtf(var + 1e-5f);

#pragma unroll
        for (int tt = 0; tt < 4; ++tt) {
            const int t = qr * 4 + tt;
            const float mu_t   = __shfl_sync(0xffffffffu, mu, tt);
            const float rstd_t = __shfl_sync(0xffffffffu, rstd, tt);
            float4 r;
            r.x = fmaf((ot[tt].x - mu_t) * rstd_t, lw.x, lb.x);
            r.y = fmaf((ot[tt].y - mu_t) * rstd_t, lw.y, lb.y);
            r.z = fmaf((ot[tt].z - mu_t) * rstd_t, lw.z, lb.z);
            r.w = fmaf((ot[tt].w - mu_t) * rstd_t, lw.w, lb.w);
            stg_stream(pO + t * (Dn / 4), r);
        }
    }
}

// ============================================================================
extern "C" void kernel_launch(void* const* d_in, const int* in_sizes, int n_in,
                              void* d_out, int out_size) {
    (void)in_sizes; (void)n_in; (void)out_size;
    const float* C    = (const float*)d_in[0];
    const float* V    = (const float*)d_in[1];
    const float* W    = (const float*)d_in[2];
    const float* enc  = (const float*)d_in[3];
    const float* tmod = (const float*)d_in[4];
    const float* cmod = (const float*)d_in[5];
    const float* lnw  = (const float*)d_in[6];
    const float* lnb  = (const float*)d_in[7];
    float* out = (float*)d_out;

    passA_kernel<<<Bn * NG, 512>>>(C, V, W, enc, tmod, cmod);     // 256 CTAs
    passB3_kernel<<<Bn * NG, 128>>>();
    passC_kernel<<<Bn * NCn / 8, 256>>>(enc, cmod, lnw, lnb, out);  // 512 CTAs
}

// round 16
// speedup vs baseline: 1.3839x; 1.0643x over previous
#include <cuda_runtime.h>
#include <cuda_fp16.h>
#include <cstdint>

// Problem constants (fixed shapes per reference)
#define Bn 16
#define Sn 4096
#define Dn 128
#define Ln 16            // timesteps per warp-chunk
#define NCn (Sn / Ln)    // 256 chunks per batch
#define GC 16            // chunks per group (scan hierarchy)
#define NG (NCn / GC)    // 16 groups per batch
#define TG (GC * Ln)     // 256 timesteps per group
#define LPL (TG / 32)    // 8 timesteps per lane in group scalar scan

// -------- scratch (device globals; no allocation allowed) --------
__device__ float g_m   [Bn * Sn];
__device__ float g_s   [Bn * Sn];
__device__ float g_P   [Bn * NCn * Dn];
__device__ float g_Q   [Bn * NCn * Dn];
__device__ float g_GP  [Bn * NG * Dn];
__device__ float g_GQ  [Bn * NG * Dn];
__device__ float g_laneM[Bn * NG * 32];
__device__ float g_laneS[Bn * NG * 32];
__device__ float g_GAM [Bn * NG];
__device__ float g_GAS [Bn * NG];
// packed replay operands: per (b,t,lane): dd0..3 as u16x4 (.x,.y), e*v as f16x4 (.z,.w)
__device__ uint4 g_dde [Bn * Sn * 32];        // 33.5 MB — fits in L2

__device__ __forceinline__ float fsig(float x) {
    return __fdividef(1.0f, 1.0f + __expf(-x));
}

// ---- reduce-scatter: v[8] per lane -> returns sum over warp of v[lane&7] --
__device__ __forceinline__ float rs8(const float* v, int lane) {
    const bool b1 = lane & 1;
    float k0 = b1 ? v[1] : v[0], o0 = b1 ? v[0] : v[1];
    float k1 = b1 ? v[3] : v[2], o1 = b1 ? v[2] : v[3];
    float k2 = b1 ? v[5] : v[4], o2 = b1 ? v[4] : v[5];
    float k3 = b1 ? v[7] : v[6], o3 = b1 ? v[6] : v[7];
    k0 += __shfl_xor_sync(0xffffffffu, o0, 1);
    k1 += __shfl_xor_sync(0xffffffffu, o1, 1);
    k2 += __shfl_xor_sync(0xffffffffu, o2, 1);
    k3 += __shfl_xor_sync(0xffffffffu, o3, 1);
    const bool b2 = lane & 2;
    float m0 = b2 ? k1 : k0, n0 = b2 ? k0 : k1;
    float m1 = b2 ? k3 : k2, n1 = b2 ? k2 : k3;
    m0 += __shfl_xor_sync(0xffffffffu, n0, 2);
    m1 += __shfl_xor_sync(0xffffffffu, n1, 2);
    const bool b4 = lane & 4;
    float p = b4 ? m1 : m0, q = b4 ? m0 : m1;
    p += __shfl_xor_sync(0xffffffffu, q, 4);
    p += __shfl_xor_sync(0xffffffffu, p, 8);
    p += __shfl_xor_sync(0xffffffffu, p, 16);
    return p;
}

// ---- reduce-scatter: 4 values -> sum over warp of v[lane&3] ---------------
__device__ __forceinline__ float rs4(float v0, float v1, float v2, float v3,
                                     int lane) {
    const bool b1 = lane & 1;
    float k0 = b1 ? v1 : v0, o0 = b1 ? v0 : v1;
    float k1 = b1 ? v3 : v2, o1 = b1 ? v2 : v3;
    k0 += __shfl_xor_sync(0xffffffffu, o0, 1);
    k1 += __shfl_xor_sync(0xffffffffu, o1, 1);
    const bool b2 = lane & 2;
    float p = b2 ? k1 : k0, q = b2 ? k0 : k1;
    p += __shfl_xor_sync(0xffffffffu, q, 2);
    p += __shfl_xor_sync(0xffffffffu, p, 4);
    p += __shfl_xor_sync(0xffffffffu, p, 8);
    p += __shfl_xor_sync(0xffffffffu, p, 16);
    return p;
}

// ---- cache-policy loads/stores ---------------------------------------------
__device__ __forceinline__ uint64_t pol_evict_last() {
    uint64_t p;
    asm("createpolicy.fractional.L2::evict_last.b64 %0, 1.0;" : "=l"(p));
    return p;
}
__device__ __forceinline__ uint64_t pol_evict_first() {
    uint64_t p;
    asm("createpolicy.fractional.L2::evict_first.b64 %0, 1.0;" : "=l"(p));
    return p;
}
__device__ __forceinline__ float4 ldg_pol(const float4* p, uint64_t pol) {
    float4 r;
    asm("ld.global.nc.L2::cache_hint.v4.f32 {%0,%1,%2,%3}, [%4], %5;"
        : "=f"(r.x), "=f"(r.y), "=f"(r.z), "=f"(r.w)
        : "l"(p), "l"(pol));
    return r;
}
__device__ __forceinline__ uint4 ldg_u4(const uint4* p) {
    uint4 r;
    asm("ld.global.nc.v4.u32 {%0,%1,%2,%3}, [%4];"
        : "=r"(r.x), "=r"(r.y), "=r"(r.z), "=r"(r.w) : "l"(p));
    return r;
}
__device__ __forceinline__ void stg_u4_keep(uint4* p, uint4 v, uint64_t pol) {
    asm volatile("st.global.L2::cache_hint.v4.u32 [%0], {%1,%2,%3,%4}, %5;"
                 :: "l"(p), "r"(v.x), "r"(v.y), "r"(v.z), "r"(v.w), "l"(pol)
                 : "memory");
}
__device__ __forceinline__ void stg_stream(float4* p, float4 v) {
    asm volatile("st.global.cs.v4.f32 [%0], {%1,%2,%3,%4};"
                 :: "l"(p), "f"(v.x), "f"(v.y), "f"(v.z), "f"(v.w) : "memory");
}

// ============================================================================
// Pass A (+B1 folded): CTA = 512 threads = 16 warps = ONE scan group.
// ============================================================================
__global__ void __launch_bounds__(512)
passA_kernel(const float* __restrict__ C, const float* __restrict__ V,
             const float* __restrict__ W, const float* __restrict__ enc,
             const float* __restrict__ tmod, const float* __restrict__ cmod) {
    __shared__ float sP[GC * Dn];     // per-chunk vector P (8 KB)
    __shared__ float sQ[GC * Dn];     // per-chunk vector Q (8 KB)
    __shared__ float sM2[32], sS2[32];  // per-half-chunk scalar aggregates

    const int wid  = threadIdx.x >> 5;
    const int lane = threadIdx.x & 31;
    const int b = blockIdx.x >> 4;          // / NG
    const int g = blockIdx.x & (NG - 1);
    const int k = g * GC + wid;
    const int t0 = k * Ln;
    const int d4 = lane * 4;

    const uint64_t polIn = pol_evict_first();
    const uint64_t polSc = pol_evict_last();

    const float4 tm = *reinterpret_cast<const float4*>(tmod + d4);
    const float4 cm = *reinterpret_cast<const float4*>(cmod + d4);
    const float4 eb = *reinterpret_cast<const float4*>(enc + b * Dn + d4);
    const float ctx0 = fsig(eb.x * cm.x) * eb.x;
    const float ctx1 = fsig(eb.y * cm.y) * eb.y;
    const float ctx2 = fsig(eb.z * cm.z) * eb.z;
    const float ctx3 = fsig(eb.w * cm.w) * eb.w;

    const size_t base = ((size_t)b * Sn + t0) * Dn + d4;
    const float4* pC = reinterpret_cast<const float4*>(C + base);
    const float4* pV = reinterpret_cast<const float4*>(V + base);
    const float4* pW = reinterpret_cast<const float4*>(W + base);
    uint4* pD = &g_dde[((size_t)b * Sn + t0) * 32 + lane];

    float P0 = 1.f, P1 = 1.f, P2 = 1.f, P3 = 1.f;
    float Q0 = 0.f, Q1 = 0.f, Q2 = 0.f, Q3 = 0.f;

#pragma unroll
    for (int half = 0; half < 2; ++half) {
        float ds[8], es[8];
#pragma unroll
        for (int tt = 0; tt < 8; ++tt) {
            const int t = half * 8 + tt;
            const float4 c = ldg_pol(pC + t * (Dn / 4), polIn);
            const float4 v = ldg_pol(pV + t * (Dn / 4), polIn);
            const float4 w = ldg_pol(pW + t * (Dn / 4), polIn);

            const float dd0 = fsig(w.x * tm.x), dd1 = fsig(w.y * tm.y);
            const float dd2 = fsig(w.z * tm.z), dd3 = fsig(w.w * tm.w);
            const float e0 = __expf(c.x), e1 = __expf(c.y);
            const float e2 = __expf(c.z), e3 = __expf(c.w);
            const float ev0 = e0 * v.x, ev1 = e1 * v.y;
            const float ev2 = e2 * v.z, ev3 = e3 * v.w;

            ds[tt] = (dd0 + dd1) + (dd2 + dd3);
            es[tt] = (e0 + e1) + (e2 + e3);

            uint4 pk;
            const uint32_t u0 = __float2uint_rn(dd0 * 65535.f);
            const uint32_t u1 = __float2uint_rn(dd1 * 65535.f);
            const uint32_t u2 = __float2uint_rn(dd2 * 65535.f);
            const uint32_t u3 = __float2uint_rn(dd3 * 65535.f);
            pk.x = u0 | (u1 << 16);
            pk.y = u2 | (u3 << 16);
            const __half2 h01 = __floats2half2_rn(ev0, ev1);
            const __half2 h23 = __floats2half2_rn(ev2, ev3);
            pk.z = *reinterpret_cast<const uint32_t*>(&h01);
            pk.w = *reinterpret_cast<const uint32_t*>(&h23);
            stg_u4_keep(pD + t * 32, pk, polSc);

            Q0 = fmaf(dd0, Q0, ev0 + ctx0);
            Q1 = fmaf(dd1, Q1, ev1 + ctx1);
            Q2 = fmaf(dd2, Q2, ev2 + ctx2);
            Q3 = fmaf(dd3, Q3, ev3 + ctx3);
            P0 *= dd0; P1 *= dd1; P2 *= dd2; P3 *= dd3;
        }
        const float msum = rs8(ds, lane);   // lane l holds sum for t = l&7
        const float ssum = rs8(es, lane);
        if (lane < 8) {
            g_m[b * Sn + t0 + half * 8 + lane] = msum * (1.0f / (float)Dn);
            g_s[b * Sn + t0 + half * 8 + lane] = ssum;
        }
        // half-chunk scalar aggregate via octet affine scan
        {
            float M = msum * (1.0f / (float)Dn);
            float S = ssum;
#pragma unroll
            for (int off = 1; off < 8; off <<= 1) {
                const float Mp = __shfl_up_sync(0xffffffffu, M, off);
                const float Sp = __shfl_up_sync(0xffffffffu, S, off);
                if ((lane & 7) >= off) { S = fmaf(M, Sp, S); M = M * Mp; }
            }
            if (lane == 7) { sM2[wid * 2 + half] = M; sS2[wid * 2 + half] = S; }
        }
    }

    const int agg = (b * NCn + k) * Dn + d4;
    *reinterpret_cast<float4*>(&g_P[agg]) = make_float4(P0, P1, P2, P3);
    *reinterpret_cast<float4*>(&g_Q[agg]) = make_float4(Q0, Q1, Q2, Q3);
    *reinterpret_cast<float4*>(&sP[wid * Dn + d4]) = make_float4(P0, P1, P2, P3);
    *reinterpret_cast<float4*>(&sQ[wid * Dn + d4]) = make_float4(Q0, Q1, Q2, Q3);
    __syncthreads();

    // ---- group vector aggregate (threads 0..127, channel d) ----
    if (threadIdx.x < Dn) {
        const int d = threadIdx.x;
        float P = 1.f, Q = 0.f;
#pragma unroll
        for (int w = 0; w < GC; ++w) {
            const float Pw = sP[w * Dn + d];
            const float Qw = sQ[w * Dn + d];
            Q = fmaf(Pw, Q, Qw);
            P *= Pw;
        }
        g_GP[(b * NG + g) * Dn + d] = P;
        g_GQ[(b * NG + g) * Dn + d] = Q;
    }

    // ---- group scalar scan (threads 128..159 = warp 4) ----
    if (threadIdx.x >= Dn && threadIdx.x < Dn + 32) {
        const int l = threadIdx.x - Dn;
        float M = sM2[l], S = sS2[l];
#pragma unroll
        for (int off = 1; off < 32; off <<= 1) {
            const float Mp = __shfl_up_sync(0xffffffffu, M, off);
            const float Sp = __shfl_up_sync(0xffffffffu, S, off);
            if (l >= off) { S = fmaf(M, Sp, S); M = M * Mp; }
        }
        float Mex = __shfl_up_sync(0xffffffffu, M, 1);
        float Sex = __shfl_up_sync(0xffffffffu, S, 1);
        if (l == 0) { Mex = 1.f; Sex = 0.f; }
        g_laneM[(b * NG + g) * 32 + l] = Mex;
        g_laneS[(b * NG + g) * 32 + l] = Sex;
        if (l == 31) {
            g_GAM[b * NG + g] = M;
            g_GAS[b * NG + g] = S;
        }
    }
}

// ============================================================================
// Pass C (+B3 folded): CTA = 512 threads = 16 warps = ONE scan group.
// Prologue (smem-staged, no big register arrays): group-exclusive vector
// prefix -> per-chunk b0 into sB0; scalar rinv for all TG timesteps into
// sRinv. Then warps replay their chunk from packed dde.
// ============================================================================
__global__ void __launch_bounds__(512)
passC_kernel(const float* __restrict__ enc, const float* __restrict__ cmod,
             const float* __restrict__ lnw, const float* __restrict__ lnb,
             float* __restrict__ out) {
    __shared__ float sA[GC * Dn];      // staging: GP then P (8 KB)
    __shared__ float sB[GC * Dn];      // staging: GQ then Q (8 KB)
    __shared__ float sB0[GC * Dn];     // per-chunk b0 (8 KB)
    __shared__ float sRinv[TG];        // per-t rinv (1 KB)

    const int tid  = threadIdx.x;
    const int wid  = tid >> 5;
    const int lane = tid & 31;
    const int b = blockIdx.x >> 4;
    const int g = blockIdx.x & (NG - 1);
    const int k = g * GC + wid;
    const int t0 = k * Ln;
    const int d4 = lane * 4;

    // ---- stage group aggregates (NG*Dn == GC*Dn floats each) ----
    for (int i = tid; i < NG * Dn; i += 512) {
        sA[i] = g_GP[b * NG * Dn + i];
        sB[i] = g_GQ[b * NG * Dn + i];
    }
    __syncthreads();

    // group-exclusive vector prefix (threads 0..127 own channel d)
    float b0 = 0.f;
    if (tid < Dn) {
#pragma unroll
        for (int gg = 0; gg < NG; ++gg) {
            if (gg < g) b0 = fmaf(sA[gg * Dn + tid], b0, sB[gg * Dn + tid]);
        }
    }
    __syncthreads();   // before buffer reuse

    // ---- stage this group's chunk P/Q ----
    for (int i = tid; i < GC * Dn; i += 512) {
        sA[i] = g_P[(b * NCn + g * GC) * Dn + i];
        sB[i] = g_Q[(b * NCn + g * GC) * Dn + i];
    }
    __syncthreads();

    if (tid < Dn) {
        // chunk rescan: exclusive b0 per chunk for channel tid
#pragma unroll
        for (int kk = 0; kk < GC; ++kk) {
            sB0[kk * Dn + tid] = b0;
            b0 = fmaf(sA[kk * Dn + tid], b0, sB[kk * Dn + tid]);
        }
    } else if (wid == 4) {
        // scalar rinv rescan (warp 4)
        const int l = lane;
        float M = 1.f, S = 0.f;
        if (l < NG) {
            M = g_GAM[b * NG + l];
            S = g_GAS[b * NG + l];
        }
#pragma unroll
        for (int off = 1; off < 16; off <<= 1) {
            const float Mp = __shfl_up_sync(0xffffffffu, M, off);
            const float Sp = __shfl_up_sync(0xffffffffu, S, off);
            if (l >= off) { S = fmaf(M, Sp, S); M = M * Mp; }
        }
        const float a0g = (g == 0) ? 0.f : __shfl_sync(0xffffffffu, S, g - 1);

        const float Mex = g_laneM[(b * NG + g) * 32 + l];
        const float Sex = g_laneS[(b * NG + g) * 32 + l];
        const int tb = b * Sn + g * TG + l * LPL;
        float mr[LPL], sr[LPL];
#pragma unroll
        for (int i = 0; i < LPL; ++i) { mr[i] = g_m[tb + i]; sr[i] = g_s[tb + i]; }
        float a = fmaf(Mex, a0g, Sex);
#pragma unroll
        for (int i = 0; i < LPL; ++i) {
            a = fmaf(mr[i], a, sr[i]);
            sRinv[l * LPL + i] = __fdividef(1.0f, a + 1e-8f);
        }
    }
    __syncthreads();

    // ---- replay: warp wid owns chunk k ----
    float rv = 0.f;
    if (lane < Ln) rv = sRinv[wid * Ln + lane];

    const float4 cm = *reinterpret_cast<const float4*>(cmod + d4);
    const float4 eb = *reinterpret_cast<const float4*>(enc + b * Dn + d4);
    const float ctx0 = fsig(eb.x * cm.x) * eb.x;
    const float ctx1 = fsig(eb.y * cm.y) * eb.y;
    const float ctx2 = fsig(eb.z * cm.z) * eb.z;
    const float ctx3 = fsig(eb.w * cm.w) * eb.w;
    const float4 lw = *reinterpret_cast<const float4*>(lnw + d4);
    const float4 lb = *reinterpret_cast<const float4*>(lnb + d4);

    float4 bst = *reinterpret_cast<const float4*>(&sB0[wid * Dn + d4]);

    const uint4* pD = &g_dde[((size_t)b * Sn + t0) * 32 + lane];
    float4* pO = reinterpret_cast<float4*>(out + ((size_t)b * Sn + t0) * Dn + d4);

    const float inv16 = 1.0f / 65535.f;

#pragma unroll
    for (int qr = 0; qr < 4; ++qr) {
        float4 ot[4];
        float ls[4], lq[4];
#pragma unroll
        for (int tt = 0; tt < 4; ++tt) {
            const int t = qr * 4 + tt;
            const uint4 pk = ldg_u4(pD + t * 32);

            const float dd0 = (float)(pk.x & 0xffffu) * inv16;
            const float dd1 = (float)(pk.x >> 16) * inv16;
            const float dd2 = (float)(pk.y & 0xffffu) * inv16;
            const float dd3 = (float)(pk.y >> 16) * inv16;
            const float2 e01 = __half22float2(*reinterpret_cast<const __half2*>(&pk.z));
            const float2 e23 = __half22float2(*reinterpret_cast<const __half2*>(&pk.w));

            bst.x = fmaf(dd0, bst.x, e01.x + ctx0);
            bst.y = fmaf(dd1, bst.y, e01.y + ctx1);
            bst.z = fmaf(dd2, bst.z, e23.x + ctx2);
            bst.w = fmaf(dd3, bst.w, e23.y + ctx3);

            const float rinv = __shfl_sync(0xffffffffu, rv, t);
            float4 o;
            o.x = bst.x * rinv; o.y = bst.y * rinv;
            o.z = bst.z * rinv; o.w = bst.w * rinv;
            ot[tt] = o;
            ls[tt] = (o.x + o.y) + (o.z + o.w);
            lq[tt] = fmaf(o.x, o.x, fmaf(o.y, o.y, fmaf(o.z, o.z, o.w * o.w)));
        }

        const float lsum = rs4(ls[0], ls[1], ls[2], ls[3], lane);
        const float lsq  = rs4(lq[0], lq[1], lq[2], lq[3], lane);
        const float mu   = lsum * (1.0f / (float)Dn);
        const float var  = fmaf(-mu, mu, lsq * (1.0f / (float)Dn));
        const float rstd = rsqrtf(var + 1e-5f);

#pragma unroll
        for (int tt = 0; tt < 4; ++tt) {
            const int t = qr * 4 + tt;
            const float mu_t   = __shfl_sync(0xffffffffu, mu, tt);
            const float rstd_t = __shfl_sync(0xffffffffu, rstd, tt);
            float4 r;
            r.x = fmaf((ot[tt].x - mu_t) * rstd_t, lw.x, lb.x);
            r.y = fmaf((ot[tt].y - mu_t) * rstd_t, lw.y, lb.y);
            r.z = fmaf((ot[tt].z - mu_t) * rstd_t, lw.z, lb.z);
            r.w = fmaf((ot[tt].w - mu_t) * rstd_t, lw.w, lb.w);
            stg_stream(pO + t * (Dn / 4), r);
        }
    }
}

// ============================================================================
extern "C" void kernel_launch(void* const* d_in, const int* in_sizes, int n_in,
                              void* d_out, int out_size) {
    (void)in_sizes; (void)n_in; (void)out_size;
    const float* C    = (const float*)d_in[0];
    const float* V    = (const float*)d_in[1];
    const float* W    = (const float*)d_in[2];
    const float* enc  = (const float*)d_in[3];
    const float* tmod = (const float*)d_in[4];
    const float* cmod = (const float*)d_in[5];
    const float* lnw  = (const float*)d_in[6];
    const float* lnb  = (const float*)d_in[7];
    float* out = (float*)d_out;

    passA_kernel<<<Bn * NG, 512>>>(C, V, W, enc, tmod, cmod);     // 256 CTAs
    passC_kernel<<<Bn * NG, 512>>>(enc, cmod, lnw, lnb, out);     // 256 CTAs
}